// round 10
// baseline (speedup 1.0000x reference)
#include <cuda_runtime.h>
#include <cuda_fp16.h>
#include <cstdint>

// Problem constants
#define N_SRC1  292864
#define N_DST1  11264
#define N_E1    281600
#define N_DST2  1024
#define N_E2    10240
#define IN_DIM  256
#define H_DIM   256
#define C_DIM   47

// Scratch (device globals — no allocation allowed)
// A = [x_dst | hneigh1] as fp16, [11264 x 512]
__device__ __half g_A[N_DST1 * 512];
// W^T = [Wself;Wneigh]^T as fp16, [256 n][512 k]
__device__ __half g_WT[256 * 512];
__device__ float g_h[N_DST1 * H_DIM];

// ---------------------------------------------------------------------------
// fp16 helpers
// ---------------------------------------------------------------------------
__device__ __forceinline__ uint32_t pack_h2(float f0, float f1) {
    const __half h0 = __float2half_rn(f0);
    const __half h1 = __float2half_rn(f1);
    return (uint32_t)__half_as_ushort(h0) | ((uint32_t)__half_as_ushort(h1) << 16);
}
__device__ __forceinline__ void store_h4(__half* p, float4 v) {
    uint2 u;
    u.x = pack_h2(v.x, v.y);
    u.y = pack_h2(v.z, v.w);
    *reinterpret_cast<uint2*>(p) = u;
}

// ---------------------------------------------------------------------------
// Layer-1 mean aggregation: 128 threads per dst node, 2-way edge split,
// 4x unroll per stream (MLP 4). Emits fp16 into A columns [256,512).
// ---------------------------------------------------------------------------
__global__ __launch_bounds__(128) void agg1_kernel(const float* __restrict__ feat,
                                                   const int* __restrict__ src_idx,
                                                   const int* __restrict__ dst_idx,
                                                   __half* __restrict__ A)
{
    const int d = blockIdx.x;

    int lo = 0, hi = N_E1;
    while (lo < hi) { int mid = (lo + hi) >> 1; if (__ldg(&dst_idx[mid]) < d) lo = mid + 1; else hi = mid; }
    const int start = lo;
    hi = N_E1;
    while (lo < hi) { int mid = (lo + hi) >> 1; if (__ldg(&dst_idx[mid]) <= d) lo = mid + 1; else hi = mid; }
    const int end = lo;

    const int t    = threadIdx.x;
    const int half = t >> 6;            // 0/1 edge-stream
    const int tt   = t & 63;            // float4 slice of 256-dim row

    __shared__ float a_nb[2][256];

    float4 a0 = make_float4(0.f,0.f,0.f,0.f);
    float4 a1 = make_float4(0.f,0.f,0.f,0.f);
    float4 a2 = make_float4(0.f,0.f,0.f,0.f);
    float4 a3 = make_float4(0.f,0.f,0.f,0.f);

    int e = start + half;
    // 4x unrolled per stream (global stride 8 = 2 streams x 4 unroll)
    for (; e + 6 < end; e += 8) {
        const int s0 = __ldg(&src_idx[e]);
        const int s1 = __ldg(&src_idx[e + 2]);
        const int s2 = __ldg(&src_idx[e + 4]);
        const int s3 = __ldg(&src_idx[e + 6]);
        const float4 v0 = *reinterpret_cast<const float4*>(&feat[(size_t)s0 * 256 + tt * 4]);
        const float4 v1 = *reinterpret_cast<const float4*>(&feat[(size_t)s1 * 256 + tt * 4]);
        const float4 v2 = *reinterpret_cast<const float4*>(&feat[(size_t)s2 * 256 + tt * 4]);
        const float4 v3 = *reinterpret_cast<const float4*>(&feat[(size_t)s3 * 256 + tt * 4]);
        a0.x += v0.x; a0.y += v0.y; a0.z += v0.z; a0.w += v0.w;
        a1.x += v1.x; a1.y += v1.y; a1.z += v1.z; a1.w += v1.w;
        a2.x += v2.x; a2.y += v2.y; a2.z += v2.z; a2.w += v2.w;
        a3.x += v3.x; a3.y += v3.y; a3.z += v3.z; a3.w += v3.w;
    }
    for (; e < end; e += 2) {
        const int s = __ldg(&src_idx[e]);
        const float4 v = *reinterpret_cast<const float4*>(&feat[(size_t)s * 256 + tt * 4]);
        a0.x += v.x; a0.y += v.y; a0.z += v.z; a0.w += v.w;
    }
    a0.x += a1.x + a2.x + a3.x;
    a0.y += a1.y + a2.y + a3.y;
    a0.z += a1.z + a2.z + a3.z;
    a0.w += a1.w + a2.w + a3.w;

    *reinterpret_cast<float4*>(&a_nb[half][tt * 4]) = a0;
    __syncthreads();

    if (half == 0) {
        const int deg = end - start;
        const float inv = (deg > 0) ? 1.0f / (float)deg : 0.0f;
        float4 u = *reinterpret_cast<float4*>(&a_nb[0][tt * 4]);
        const float4 w = *reinterpret_cast<float4*>(&a_nb[1][tt * 4]);
        u.x = (u.x + w.x) * inv; u.y = (u.y + w.y) * inv;
        u.z = (u.z + w.z) * inv; u.w = (u.w + w.w) * inv;
        store_h4(&A[(size_t)d * 512 + 256 + tt * 4], u);
    }
}

// ---------------------------------------------------------------------------
// Convert x[:11264] into A columns [0,256) (fp16).
// ---------------------------------------------------------------------------
__global__ __launch_bounds__(256) void xcvt_kernel(const float* __restrict__ x,
                                                   __half* __restrict__ A)
{
    const int idx = blockIdx.x * 256 + threadIdx.x;
    const int r  = idx >> 6;
    const int c4 = (idx & 63) * 4;
    const float4 v = *reinterpret_cast<const float4*>(&x[(size_t)r * 256 + c4]);
    store_h4(&A[(size_t)r * 512 + c4], v);
}

// ---------------------------------------------------------------------------
// Transpose + convert W: WT[n][k]
// ---------------------------------------------------------------------------
__global__ __launch_bounds__(256) void wcvt_kernel(const float* __restrict__ Wself,
                                                   const float* __restrict__ Wneigh,
                                                   __half* __restrict__ WT)
{
    const int idx = blockIdx.x * 256 + threadIdx.x;
    const int n = idx >> 9;
    const int k = idx & 511;
    const float v = (k < 256) ? __ldg(&Wself[(size_t)k * 256 + n])
                              : __ldg(&Wneigh[(size_t)(k - 256) * 256 + n]);
    WT[(size_t)n * 512 + k] = __float2half_rn(v);
}

// ---------------------------------------------------------------------------
// cp.async / ldmatrix helpers
// ---------------------------------------------------------------------------
__device__ __forceinline__ void cp_async16(uint32_t saddr, const void* g) {
    asm volatile("cp.async.ca.shared.global [%0], [%1], 16;\n" :: "r"(saddr), "l"(g));
}
__device__ __forceinline__ void cp_commit() {
    asm volatile("cp.async.commit_group;\n" ::: "memory");
}
__device__ __forceinline__ void ldsm_x4(uint32_t& r0, uint32_t& r1, uint32_t& r2, uint32_t& r3,
                                        uint32_t addr) {
    asm volatile("ldmatrix.sync.aligned.m8n8.x4.shared.b16 {%0,%1,%2,%3}, [%4];\n"
                 : "=r"(r0), "=r"(r1), "=r"(r2), "=r"(r3) : "r"(addr));
}
__device__ __forceinline__ void mma_f16(float c[4], const uint32_t a[4], const uint32_t b[2]) {
    asm volatile(
        "mma.sync.aligned.m16n8k16.row.col.f32.f16.f16.f32 "
        "{%0,%1,%2,%3}, {%4,%5,%6,%7}, {%8,%9}, {%0,%1,%2,%3};\n"
        : "+f"(c[0]), "+f"(c[1]), "+f"(c[2]), "+f"(c[3])
        : "r"(a[0]), "r"(a[1]), "r"(a[2]), "r"(a[3]), "r"(b[0]), "r"(b[1]));
}

// ---------------------------------------------------------------------------
// Layer-1 GEMM: h = relu(A @ WT^T + b), single-pass fp16 mma.m16n8k16.
// CTA 128x64, BK=32, 8 warps (warp 32x32), 3-stage cp.async ring + ldmatrix.
// Shared rows: 20-word (80B) stride -> conflict-free LDSM phases.
// ---------------------------------------------------------------------------
#define G1_BM 128
#define G1_BN 64
#define G1_BK 32
#define SRW 20
#define OFF_A 0
#define OFF_B (G1_BM * SRW)
#define STAGE_WORDS ((G1_BM + G1_BN) * SRW)
#define N_KTILES 16

__global__ __launch_bounds__(256) void gemm1_kernel(
    const __half* __restrict__ A,
    const __half* __restrict__ WT,
    const float* __restrict__ bias,
    float* __restrict__ out)
{
    const int bx = blockIdx.x;
    const int by = blockIdx.y;

    const int tid  = threadIdx.x;
    const int warp = tid >> 5;
    const int lane = tid & 31;
    const int wm   = warp >> 1;
    const int wn   = warp & 1;
    const int g    = lane >> 2;
    const int tg   = lane & 3;

    __shared__ __align__(16) uint32_t smem[3 * STAGE_WORDS];

    uint32_t sbase;
    asm("{ .reg .u64 t; cvta.to.shared.u64 t, %1; cvt.u32.u64 %0, t; }"
        : "=r"(sbase) : "l"(smem));

    const int a_row0 = tid >> 2;
    const int a_ch   = tid & 3;
    const int b_row  = tid >> 2;
    const int b_ch   = tid & 3;

    const __half* gA0 = A  + (size_t)(by * G1_BM + a_row0) * 512 + a_ch * 8;
    const __half* gA1 = A  + (size_t)(by * G1_BM + a_row0 + 64) * 512 + a_ch * 8;
    const __half* gB  = WT + (size_t)(bx * G1_BN + b_row) * 512 + b_ch * 8;

    const uint32_t sA0 = sbase + (OFF_A + a_row0 * SRW + a_ch * 4) * 4;
    const uint32_t sA1 = sbase + (OFF_A + (a_row0 + 64) * SRW + a_ch * 4) * 4;
    const uint32_t sB  = sbase + (OFF_B + b_row * SRW + b_ch * 4) * 4;

    uint32_t aAddr[2];
#pragma unroll
    for (int i = 0; i < 2; ++i) {
        const int row = wm * 32 + i * 16 + (lane & 15);
        const int word = (lane >> 4) * 4;
        aAddr[i] = sbase + (OFF_A + row * SRW + word) * 4;
    }
    uint32_t bAddr[2];
#pragma unroll
    for (int p = 0; p < 2; ++p) {
        const int row = wn * 32 + p * 16 + (lane & 7) + ((lane >> 4) << 3);
        const int word = ((lane >> 3) & 1) * 4;
        bAddr[p] = sbase + (OFF_B + row * SRW + word) * 4;
    }
    const uint32_t stage_bytes = STAGE_WORDS * 4;

    float acc[2][4][4];
#pragma unroll
    for (int i = 0; i < 2; ++i)
#pragma unroll
        for (int j = 0; j < 4; ++j)
#pragma unroll
            for (int r = 0; r < 4; ++r) acc[i][j][r] = 0.f;

#pragma unroll
    for (int pt = 0; pt < 2; ++pt) {
        const uint32_t so = pt * stage_bytes;
        const int kn = pt * G1_BK;
        cp_async16(sA0 + so, gA0 + kn);
        cp_async16(sA1 + so, gA1 + kn);
        cp_async16(sB + so,  gB + kn);
        cp_commit();
    }

    int stage = 0;
    for (int t = 0; t < N_KTILES; ++t) {
        if (t + 1 < N_KTILES)
            asm volatile("cp.async.wait_group 1;" ::: "memory");
        else
            asm volatile("cp.async.wait_group 0;" ::: "memory");
        __syncthreads();

        if (t + 2 < N_KTILES) {
            const int kn = (t + 2) * G1_BK;
            const uint32_t so = ((stage + 2) % 3) * stage_bytes;
            cp_async16(sA0 + so, gA0 + kn);
            cp_async16(sA1 + so, gA1 + kn);
            cp_async16(sB + so,  gB + kn);
            cp_commit();
        }

        const uint32_t so = stage * stage_bytes;
#pragma unroll
        for (int s = 0; s < 2; ++s) {
            const uint32_t ko = so + s * 32;
            uint32_t Af[2][4], Bf[2][4];
#pragma unroll
            for (int i = 0; i < 2; ++i)
                ldsm_x4(Af[i][0], Af[i][1], Af[i][2], Af[i][3], aAddr[i] + ko);
#pragma unroll
            for (int p = 0; p < 2; ++p)
                ldsm_x4(Bf[p][0], Bf[p][1], Bf[p][2], Bf[p][3], bAddr[p] + ko);
#pragma unroll
            for (int i = 0; i < 2; ++i)
#pragma unroll
                for (int j = 0; j < 4; ++j) {
                    const uint32_t bf[2] = { Bf[j >> 1][(j & 1) * 2], Bf[j >> 1][(j & 1) * 2 + 1] };
                    mma_f16(acc[i][j], Af[i], bf);
                }
        }
        stage = (stage + 1) % 3;
    }

#pragma unroll
    for (int i = 0; i < 2; ++i) {
#pragma unroll
        for (int j = 0; j < 4; ++j) {
            const int col = bx * G1_BN + wn * 32 + j * 8 + tg * 2;
            const float b0 = __ldg(&bias[col]);
            const float b1 = __ldg(&bias[col + 1]);
            const int r0 = by * G1_BM + wm * 32 + i * 16 + g;
            float2 v0;
            v0.x = fmaxf(acc[i][j][0] + b0, 0.f);
            v0.y = fmaxf(acc[i][j][1] + b1, 0.f);
            *reinterpret_cast<float2*>(&out[(size_t)r0 * 256 + col]) = v0;
            float2 v1;
            v1.x = fmaxf(acc[i][j][2] + b0, 0.f);
            v1.y = fmaxf(acc[i][j][3] + b1, 0.f);
            *reinterpret_cast<float2*>(&out[(size_t)(r0 + 8) * 256 + col]) = v1;
        }
    }
}

// ---------------------------------------------------------------------------
// Fused layer 2: gather-mean + tiny GEMM per output row.
// ---------------------------------------------------------------------------
__global__ __launch_bounds__(128) void layer2_fused_kernel(
    const float* __restrict__ h,
    const int* __restrict__ src2,
    const int* __restrict__ dst2,
    const float* __restrict__ Ws,
    const float* __restrict__ Wn,
    const float* __restrict__ bias,
    float* __restrict__ out)
{
    const int d = blockIdx.x;

    int lo = 0, hi = N_E2;
    while (lo < hi) { int mid = (lo + hi) >> 1; if (__ldg(&dst2[mid]) < d) lo = mid + 1; else hi = mid; }
    const int start = lo;
    hi = N_E2;
    while (lo < hi) { int mid = (lo + hi) >> 1; if (__ldg(&dst2[mid]) <= d) lo = mid + 1; else hi = mid; }
    const int end = lo;

    __shared__ float a_self[256];
    __shared__ float a_nb[2][256];
    __shared__ float part[94];

    const int t    = threadIdx.x;
    const int half = t >> 6;
    const int tt   = t & 63;

    if (half == 0) {
        *reinterpret_cast<float4*>(&a_self[tt * 4]) =
            *reinterpret_cast<const float4*>(&h[(size_t)d * 256 + tt * 4]);
    }

    float4 acc = make_float4(0.f, 0.f, 0.f, 0.f);
    for (int e = start + half; e < end; e += 2) {
        const int s = __ldg(&src2[e]);
        const float4 v = *reinterpret_cast<const float4*>(&h[(size_t)s * 256 + tt * 4]);
        acc.x += v.x; acc.y += v.y; acc.z += v.z; acc.w += v.w;
    }
    *reinterpret_cast<float4*>(&a_nb[half][tt * 4]) = acc;
    __syncthreads();

    const int deg = end - start;
    const float inv = (deg > 0) ? 1.0f / (float)deg : 0.0f;
    if (half == 0) {
        float4 u = *reinterpret_cast<float4*>(&a_nb[0][tt * 4]);
        const float4 w = *reinterpret_cast<float4*>(&a_nb[1][tt * 4]);
        u.x = (u.x + w.x) * inv; u.y = (u.y + w.y) * inv;
        u.z = (u.z + w.z) * inv; u.w = (u.w + w.w) * inv;
        *reinterpret_cast<float4*>(&a_nb[0][tt * 4]) = u;
    }
    __syncthreads();

    if (t < 94) {
        const int c  = (t < 47) ? t : t - 47;
        const int kb = (t < 47) ? 0 : 128;
        const float* as = &a_self[kb];
        const float* an = &a_nb[0][kb];
        float accS = 0.f, accN = 0.f;
#pragma unroll 8
        for (int k = 0; k < 128; ++k) {
            accS += as[k] * __ldg(&Ws[(size_t)(kb + k) * 47 + c]);
            accN += an[k] * __ldg(&Wn[(size_t)(kb + k) * 47 + c]);
        }
        part[t] = accS + accN;
    }
    __syncthreads();

    if (t < 47) {
        out[(size_t)d * 47 + t] = part[t] + part[t + 47] + __ldg(&bias[t]);
    }
}

// ---------------------------------------------------------------------------
// Launch
// ---------------------------------------------------------------------------
extern "C" void kernel_launch(void* const* d_in, const int* in_sizes, int n_in,
                              void* d_out, int out_size)
{
    const float* x       = (const float*)d_in[0];
    const int*   src1    = (const int*)  d_in[1];
    const int*   dst1    = (const int*)  d_in[2];
    const int*   src2    = (const int*)  d_in[3];
    const int*   dst2    = (const int*)  d_in[4];
    const float* Wself1  = (const float*)d_in[5];
    const float* Wneigh1 = (const float*)d_in[6];
    const float* b1      = (const float*)d_in[7];
    const float* Wself2  = (const float*)d_in[8];
    const float* Wneigh2 = (const float*)d_in[9];
    const float* b2      = (const float*)d_in[10];
    float* out = (float*)d_out;

    __half *A, *WT;
    float* hbuf;
    cudaGetSymbolAddress((void**)&A,  g_A);
    cudaGetSymbolAddress((void**)&WT, g_WT);
    cudaGetSymbolAddress((void**)&hbuf, g_h);

    // Prep: W transpose+convert, x convert, neighbor mean (+convert)
    wcvt_kernel<<<(256 * 512) / 256, 256>>>(Wself1, Wneigh1, WT);
    xcvt_kernel<<<(N_DST1 * 64) / 256, 256>>>(x, A);
    agg1_kernel<<<N_DST1, 128>>>(x, src1, dst1, A);

    // Layer 1 GEMM + bias + relu (single-pass fp16)
    dim3 g1(H_DIM / G1_BN, N_DST1 / G1_BM);   // (4, 88)
    gemm1_kernel<<<g1, 256>>>(A, WT, b1, hbuf);

    // Fused layer 2
    layer2_fused_kernel<<<N_DST2, 128>>>(hbuf, src2, dst2, Wself2, Wneigh2, b2, out);
}

// round 11
// speedup vs baseline: 1.1796x; 1.1796x over previous
#include <cuda_runtime.h>
#include <cuda_fp16.h>
#include <cstdint>

// Problem constants
#define N_SRC1  292864
#define N_DST1  11264
#define N_E1    281600
#define N_DST2  1024
#define N_E2    10240
#define IN_DIM  256
#define H_DIM   256
#define C_DIM   47

// Scratch (device globals — no allocation allowed)
__device__ __half g_A[N_DST1 * 512];      // [x_dst | hneigh1] fp16
__device__ __half g_WT[256 * 512];        // [Wself1;Wneigh1]^T fp16
__device__ float  g_h[N_DST1 * H_DIM];    // relu(layer-1 out) fp32
__device__ __half g_A2[N_DST2 * 512];     // [h_dst | hneigh2] fp16
__device__ __half g_WT2[64 * 512];        // [Wself2;Wneigh2]^T fp16, cols 47-63 zero

// ---------------------------------------------------------------------------
// fp16 helpers
// ---------------------------------------------------------------------------
__device__ __forceinline__ uint32_t pack_h2(float f0, float f1) {
    const __half h0 = __float2half_rn(f0);
    const __half h1 = __float2half_rn(f1);
    return (uint32_t)__half_as_ushort(h0) | ((uint32_t)__half_as_ushort(h1) << 16);
}
__device__ __forceinline__ void store_h4(__half* p, float4 v) {
    uint2 u;
    u.x = pack_h2(v.x, v.y);
    u.y = pack_h2(v.z, v.w);
    *reinterpret_cast<uint2*>(p) = u;
}

// ---------------------------------------------------------------------------
// Layer-1 mean aggregation (R9 shape): 64 thr/dst, 8x unroll. fp16 out.
// ---------------------------------------------------------------------------
__global__ __launch_bounds__(64) void agg1_kernel(const float* __restrict__ feat,
                                                  const int* __restrict__ src_idx,
                                                  const int* __restrict__ dst_idx,
                                                  __half* __restrict__ A)
{
    const int d = blockIdx.x;

    int lo = 0, hi = N_E1;
    while (lo < hi) { int mid = (lo + hi) >> 1; if (__ldg(&dst_idx[mid]) < d) lo = mid + 1; else hi = mid; }
    const int start = lo;
    hi = N_E1;
    while (lo < hi) { int mid = (lo + hi) >> 1; if (__ldg(&dst_idx[mid]) <= d) lo = mid + 1; else hi = mid; }
    const int end = lo;

    const int t = threadIdx.x;

    float4 acc[8];
#pragma unroll
    for (int u = 0; u < 8; ++u) acc[u] = make_float4(0.f, 0.f, 0.f, 0.f);

    int e = start;
    for (; e + 7 < end; e += 8) {
        int s[8];
#pragma unroll
        for (int u = 0; u < 8; ++u) s[u] = __ldg(&src_idx[e + u]);
#pragma unroll
        for (int u = 0; u < 8; ++u) {
            const float4 v = *reinterpret_cast<const float4*>(&feat[(size_t)s[u] * 256 + t * 4]);
            acc[u].x += v.x; acc[u].y += v.y; acc[u].z += v.z; acc[u].w += v.w;
        }
    }
    for (; e < end; ++e) {
        const int s = __ldg(&src_idx[e]);
        const float4 v = *reinterpret_cast<const float4*>(&feat[(size_t)s * 256 + t * 4]);
        acc[0].x += v.x; acc[0].y += v.y; acc[0].z += v.z; acc[0].w += v.w;
    }
#pragma unroll
    for (int u = 1; u < 8; ++u) {
        acc[0].x += acc[u].x; acc[0].y += acc[u].y;
        acc[0].z += acc[u].z; acc[0].w += acc[u].w;
    }

    const int deg = end - start;
    const float inv = (deg > 0) ? 1.0f / (float)deg : 0.0f;
    acc[0].x *= inv; acc[0].y *= inv; acc[0].z *= inv; acc[0].w *= inv;

    store_h4(&A[(size_t)d * 512 + 256 + t * 4], acc[0]);
}

// ---------------------------------------------------------------------------
// Layer-2 aggregation + self copy: 1024 blocks x 64 thr.
// A2[d][0:256) = fp16(h[d]); A2[d][256:512) = fp16(mean of gathered h rows).
// ---------------------------------------------------------------------------
__global__ __launch_bounds__(64) void agg2_kernel(const float* __restrict__ h,
                                                  const int* __restrict__ src_idx,
                                                  const int* __restrict__ dst_idx,
                                                  __half* __restrict__ A2)
{
    const int d = blockIdx.x;

    int lo = 0, hi = N_E2;
    while (lo < hi) { int mid = (lo + hi) >> 1; if (__ldg(&dst_idx[mid]) < d) lo = mid + 1; else hi = mid; }
    const int start = lo;
    hi = N_E2;
    while (lo < hi) { int mid = (lo + hi) >> 1; if (__ldg(&dst_idx[mid]) <= d) lo = mid + 1; else hi = mid; }
    const int end = lo;

    const int t = threadIdx.x;

    // self copy
    {
        const float4 v = *reinterpret_cast<const float4*>(&h[(size_t)d * 256 + t * 4]);
        store_h4(&A2[(size_t)d * 512 + t * 4], v);
    }

    float4 acc[4];
#pragma unroll
    for (int u = 0; u < 4; ++u) acc[u] = make_float4(0.f, 0.f, 0.f, 0.f);

    int e = start;
    for (; e + 3 < end; e += 4) {
        int s[4];
#pragma unroll
        for (int u = 0; u < 4; ++u) s[u] = __ldg(&src_idx[e + u]);
#pragma unroll
        for (int u = 0; u < 4; ++u) {
            const float4 v = *reinterpret_cast<const float4*>(&h[(size_t)s[u] * 256 + t * 4]);
            acc[u].x += v.x; acc[u].y += v.y; acc[u].z += v.z; acc[u].w += v.w;
        }
    }
    for (; e < end; ++e) {
        const int s = __ldg(&src_idx[e]);
        const float4 v = *reinterpret_cast<const float4*>(&h[(size_t)s * 256 + t * 4]);
        acc[0].x += v.x; acc[0].y += v.y; acc[0].z += v.z; acc[0].w += v.w;
    }
#pragma unroll
    for (int u = 1; u < 4; ++u) {
        acc[0].x += acc[u].x; acc[0].y += acc[u].y;
        acc[0].z += acc[u].z; acc[0].w += acc[u].w;
    }

    const int deg = end - start;
    const float inv = (deg > 0) ? 1.0f / (float)deg : 0.0f;
    acc[0].x *= inv; acc[0].y *= inv; acc[0].z *= inv; acc[0].w *= inv;

    store_h4(&A2[(size_t)d * 512 + 256 + t * 4], acc[0]);
}

// ---------------------------------------------------------------------------
// Convert x[:11264] into A columns [0,256) (fp16).
// ---------------------------------------------------------------------------
__global__ __launch_bounds__(256) void xcvt_kernel(const float* __restrict__ x,
                                                   __half* __restrict__ A)
{
    const int idx = blockIdx.x * 256 + threadIdx.x;
    const int r  = idx >> 6;
    const int c4 = (idx & 63) * 4;
    const float4 v = *reinterpret_cast<const float4*>(&x[(size_t)r * 256 + c4]);
    store_h4(&A[(size_t)r * 512 + c4], v);
}

// ---------------------------------------------------------------------------
// Transpose + convert W1: WT[n][k]
// ---------------------------------------------------------------------------
__global__ __launch_bounds__(256) void wcvt_kernel(const float* __restrict__ Wself,
                                                   const float* __restrict__ Wneigh,
                                                   __half* __restrict__ WT)
{
    const int idx = blockIdx.x * 256 + threadIdx.x;
    const int n = idx >> 9;
    const int k = idx & 511;
    const float v = (k < 256) ? __ldg(&Wself[(size_t)k * 256 + n])
                              : __ldg(&Wneigh[(size_t)(k - 256) * 256 + n]);
    WT[(size_t)n * 512 + k] = __float2half_rn(v);
}

// ---------------------------------------------------------------------------
// Transpose + convert W2 into padded [64][512]: cols >= 47 zero.
// ---------------------------------------------------------------------------
__global__ __launch_bounds__(256) void w2cvt_kernel(const float* __restrict__ Ws,
                                                    const float* __restrict__ Wn,
                                                    __half* __restrict__ WT2)
{
    const int idx = blockIdx.x * 256 + threadIdx.x;   // 64*512 = 32768
    const int n = idx >> 9;
    const int k = idx & 511;
    float v = 0.f;
    if (n < C_DIM)
        v = (k < 256) ? __ldg(&Ws[(size_t)k * C_DIM + n])
                      : __ldg(&Wn[(size_t)(k - 256) * C_DIM + n]);
    WT2[(size_t)n * 512 + k] = __float2half_rn(v);
}

// ---------------------------------------------------------------------------
// cp.async / ldmatrix helpers
// ---------------------------------------------------------------------------
__device__ __forceinline__ void cp_async16(uint32_t saddr, const void* g) {
    asm volatile("cp.async.ca.shared.global [%0], [%1], 16;\n" :: "r"(saddr), "l"(g));
}
__device__ __forceinline__ void cp_commit() {
    asm volatile("cp.async.commit_group;\n" ::: "memory");
}
__device__ __forceinline__ void ldsm_x4(uint32_t& r0, uint32_t& r1, uint32_t& r2, uint32_t& r3,
                                        uint32_t addr) {
    asm volatile("ldmatrix.sync.aligned.m8n8.x4.shared.b16 {%0,%1,%2,%3}, [%4];\n"
                 : "=r"(r0), "=r"(r1), "=r"(r2), "=r"(r3) : "r"(addr));
}
__device__ __forceinline__ void mma_f16(float c[4], const uint32_t a[4], const uint32_t b[2]) {
    asm volatile(
        "mma.sync.aligned.m16n8k16.row.col.f32.f16.f16.f32 "
        "{%0,%1,%2,%3}, {%4,%5,%6,%7}, {%8,%9}, {%0,%1,%2,%3};\n"
        : "+f"(c[0]), "+f"(c[1]), "+f"(c[2]), "+f"(c[3])
        : "r"(a[0]), "r"(a[1]), "r"(a[2]), "r"(a[3]), "r"(b[0]), "r"(b[1]));
}

// ---------------------------------------------------------------------------
// Shared fp16 MMA mainloop (CTA 128x64, BK=32, 3-stage cp.async ring).
// ---------------------------------------------------------------------------
#define G1_BM 128
#define G1_BN 64
#define G1_BK 32
#define SRW 20
#define OFF_A 0
#define OFF_B (G1_BM * SRW)
#define STAGE_WORDS ((G1_BM + G1_BN) * SRW)
#define N_KTILES 16

struct MmaCtx {
    float acc[2][4][4];
    int wm, wn, g, tg;
};

// Runs the full K=512 mainloop for one 128x64 tile. Arow = A + rowbase*512.
__device__ __forceinline__ void run_mma_tile(
    const __half* __restrict__ Abase,   // A tile base (row 0 of this CTA tile)
    const __half* __restrict__ Bbase,   // WT base (row 0 of the 64-col tile)
    uint32_t* smem, MmaCtx& ctx)
{
    const int tid  = threadIdx.x;
    const int warp = tid >> 5;
    const int lane = tid & 31;
    ctx.wm = warp >> 1;
    ctx.wn = warp & 1;
    ctx.g  = lane >> 2;
    ctx.tg = lane & 3;

    uint32_t sbase;
    asm("{ .reg .u64 t; cvta.to.shared.u64 t, %1; cvt.u32.u64 %0, t; }"
        : "=r"(sbase) : "l"(smem));

    const int a_row0 = tid >> 2;
    const int a_ch   = tid & 3;

    const __half* gA0 = Abase + (size_t)a_row0 * 512 + a_ch * 8;
    const __half* gA1 = Abase + (size_t)(a_row0 + 64) * 512 + a_ch * 8;
    const __half* gB  = Bbase + (size_t)a_row0 * 512 + a_ch * 8;   // 64 rows

    const uint32_t sA0 = sbase + (OFF_A + a_row0 * SRW + a_ch * 4) * 4;
    const uint32_t sA1 = sbase + (OFF_A + (a_row0 + 64) * SRW + a_ch * 4) * 4;
    const uint32_t sB  = sbase + (OFF_B + a_row0 * SRW + a_ch * 4) * 4;

    uint32_t aAddr[2];
#pragma unroll
    for (int i = 0; i < 2; ++i) {
        const int row = ctx.wm * 32 + i * 16 + (lane & 15);
        const int word = (lane >> 4) * 4;
        aAddr[i] = sbase + (OFF_A + row * SRW + word) * 4;
    }
    uint32_t bAddr[2];
#pragma unroll
    for (int p = 0; p < 2; ++p) {
        const int row = ctx.wn * 32 + p * 16 + (lane & 7) + ((lane >> 4) << 3);
        const int word = ((lane >> 3) & 1) * 4;
        bAddr[p] = sbase + (OFF_B + row * SRW + word) * 4;
    }
    const uint32_t stage_bytes = STAGE_WORDS * 4;

#pragma unroll
    for (int i = 0; i < 2; ++i)
#pragma unroll
        for (int j = 0; j < 4; ++j)
#pragma unroll
            for (int r = 0; r < 4; ++r) ctx.acc[i][j][r] = 0.f;

#pragma unroll
    for (int pt = 0; pt < 2; ++pt) {
        const uint32_t so = pt * stage_bytes;
        const int kn = pt * G1_BK;
        cp_async16(sA0 + so, gA0 + kn);
        cp_async16(sA1 + so, gA1 + kn);
        cp_async16(sB + so,  gB + kn);
        cp_commit();
    }

    int stage = 0;
    for (int t = 0; t < N_KTILES; ++t) {
        if (t + 1 < N_KTILES)
            asm volatile("cp.async.wait_group 1;" ::: "memory");
        else
            asm volatile("cp.async.wait_group 0;" ::: "memory");
        __syncthreads();

        if (t + 2 < N_KTILES) {
            const int kn = (t + 2) * G1_BK;
            const uint32_t so = ((stage + 2) % 3) * stage_bytes;
            cp_async16(sA0 + so, gA0 + kn);
            cp_async16(sA1 + so, gA1 + kn);
            cp_async16(sB + so,  gB + kn);
            cp_commit();
        }

        const uint32_t so = stage * stage_bytes;
#pragma unroll
        for (int s = 0; s < 2; ++s) {
            const uint32_t ko = so + s * 32;
            uint32_t Af[2][4], Bf[2][4];
#pragma unroll
            for (int i = 0; i < 2; ++i)
                ldsm_x4(Af[i][0], Af[i][1], Af[i][2], Af[i][3], aAddr[i] + ko);
#pragma unroll
            for (int p = 0; p < 2; ++p)
                ldsm_x4(Bf[p][0], Bf[p][1], Bf[p][2], Bf[p][3], bAddr[p] + ko);
#pragma unroll
            for (int i = 0; i < 2; ++i)
#pragma unroll
                for (int j = 0; j < 4; ++j) {
                    const uint32_t bf[2] = { Bf[j >> 1][(j & 1) * 2], Bf[j >> 1][(j & 1) * 2 + 1] };
                    mma_f16(ctx.acc[i][j], Af[i], bf);
                }
        }
        stage = (stage + 1) % 3;
    }
}

// ---------------------------------------------------------------------------
// Layer-1 GEMM: h = relu(A @ WT^T + b1)
// ---------------------------------------------------------------------------
__global__ __launch_bounds__(256) void gemm1_kernel(
    const __half* __restrict__ A,
    const __half* __restrict__ WT,
    const float* __restrict__ bias,
    float* __restrict__ out)
{
    __shared__ __align__(16) uint32_t smem[3 * STAGE_WORDS];
    const int bx = blockIdx.x;
    const int by = blockIdx.y;

    MmaCtx ctx;
    run_mma_tile(A + (size_t)(by * G1_BM) * 512, WT + (size_t)(bx * G1_BN) * 512, smem, ctx);

#pragma unroll
    for (int i = 0; i < 2; ++i) {
#pragma unroll
        for (int j = 0; j < 4; ++j) {
            const int col = bx * G1_BN + ctx.wn * 32 + j * 8 + ctx.tg * 2;
            const float b0 = __ldg(&bias[col]);
            const float b1 = __ldg(&bias[col + 1]);
            const int r0 = by * G1_BM + ctx.wm * 32 + i * 16 + ctx.g;
            float2 v0;
            v0.x = fmaxf(ctx.acc[i][j][0] + b0, 0.f);
            v0.y = fmaxf(ctx.acc[i][j][1] + b1, 0.f);
            *reinterpret_cast<float2*>(&out[(size_t)r0 * 256 + col]) = v0;
            float2 v1;
            v1.x = fmaxf(ctx.acc[i][j][2] + b0, 0.f);
            v1.y = fmaxf(ctx.acc[i][j][3] + b1, 0.f);
            *reinterpret_cast<float2*>(&out[(size_t)(r0 + 8) * 256 + col]) = v1;
        }
    }
}

// ---------------------------------------------------------------------------
// Layer-2 GEMM: out = A2 @ WT2^T + b2 (no relu), cols >= 47 dropped.
// grid = 8 (M tiles), single 64-col tile.
// ---------------------------------------------------------------------------
__global__ __launch_bounds__(256) void gemm2_tc_kernel(
    const __half* __restrict__ A2,
    const __half* __restrict__ WT2,
    const float* __restrict__ bias,
    float* __restrict__ out)
{
    __shared__ __align__(16) uint32_t smem[3 * STAGE_WORDS];
    const int by = blockIdx.x;

    MmaCtx ctx;
    run_mma_tile(A2 + (size_t)(by * G1_BM) * 512, WT2, smem, ctx);

#pragma unroll
    for (int i = 0; i < 2; ++i) {
#pragma unroll
        for (int j = 0; j < 4; ++j) {
            const int col = ctx.wn * 32 + j * 8 + ctx.tg * 2;
            const int r0 = by * G1_BM + ctx.wm * 32 + i * 16 + ctx.g;
            if (col < C_DIM) {
                const float b0 = __ldg(&bias[col]);
                out[(size_t)r0 * C_DIM + col]       = ctx.acc[i][j][0] + b0;
                out[(size_t)(r0 + 8) * C_DIM + col] = ctx.acc[i][j][2] + b0;
            }
            if (col + 1 < C_DIM) {
                const float b1 = __ldg(&bias[col + 1]);
                out[(size_t)r0 * C_DIM + col + 1]       = ctx.acc[i][j][1] + b1;
                out[(size_t)(r0 + 8) * C_DIM + col + 1] = ctx.acc[i][j][3] + b1;
            }
        }
    }
}

// ---------------------------------------------------------------------------
// Launch
// ---------------------------------------------------------------------------
extern "C" void kernel_launch(void* const* d_in, const int* in_sizes, int n_in,
                              void* d_out, int out_size)
{
    const float* x       = (const float*)d_in[0];
    const int*   src1    = (const int*)  d_in[1];
    const int*   dst1    = (const int*)  d_in[2];
    const int*   src2    = (const int*)  d_in[3];
    const int*   dst2    = (const int*)  d_in[4];
    const float* Wself1  = (const float*)d_in[5];
    const float* Wneigh1 = (const float*)d_in[6];
    const float* b1      = (const float*)d_in[7];
    const float* Wself2  = (const float*)d_in[8];
    const float* Wneigh2 = (const float*)d_in[9];
    const float* b2      = (const float*)d_in[10];
    float* out = (float*)d_out;

    __half *A, *WT, *A2, *WT2;
    float* hbuf;
    cudaGetSymbolAddress((void**)&A,   g_A);
    cudaGetSymbolAddress((void**)&WT,  g_WT);
    cudaGetSymbolAddress((void**)&A2,  g_A2);
    cudaGetSymbolAddress((void**)&WT2, g_WT2);
    cudaGetSymbolAddress((void**)&hbuf, g_h);

    // Prep (all independent of agg/gemm chain)
    wcvt_kernel<<<(256 * 512) / 256, 256>>>(Wself1, Wneigh1, WT);
    w2cvt_kernel<<<(64 * 512) / 256, 256>>>(Wself2, Wneigh2, WT2);
    xcvt_kernel<<<(N_DST1 * 64) / 256, 256>>>(x, A);
    agg1_kernel<<<N_DST1, 64>>>(x, src1, dst1, A);

    // Layer 1 GEMM + bias + relu
    dim3 g1(H_DIM / G1_BN, N_DST1 / G1_BM);   // (4, 88)
    gemm1_kernel<<<g1, 256>>>(A, WT, b1, hbuf);

    // Layer 2: aggregate + GEMM
    agg2_kernel<<<N_DST2, 64>>>(hbuf, src2, dst2, A2);
    gemm2_tc_kernel<<<N_DST2 / G1_BM, 256>>>(A2, WT2, b2, out);
}

// round 12
// speedup vs baseline: 1.2742x; 1.0802x over previous
#include <cuda_runtime.h>
#include <cuda_fp16.h>
#include <cstdint>

// Problem constants
#define N_SRC1  292864
#define N_DST1  11264
#define N_E1    281600
#define N_DST2  1024
#define N_E2    10240
#define IN_DIM  256
#define H_DIM   256
#define C_DIM   47

// Scratch (device globals — no allocation allowed)
__device__ __half g_A[N_DST1 * 512];      // [x_dst | hneigh1] fp16
__device__ __half g_WT[256 * 512];        // [Wself1;Wneigh1]^T fp16
__device__ float  g_h[N_DST1 * H_DIM];    // relu(layer-1 out) fp32
__device__ __half g_A2[N_DST2 * 512];     // [h_dst | hneigh2] fp16
__device__ __half g_WT2[64 * 512];        // [Wself2;Wneigh2]^T fp16, cols 47-63 zero

// ---------------------------------------------------------------------------
// fp16 helpers
// ---------------------------------------------------------------------------
__device__ __forceinline__ uint32_t pack_h2(float f0, float f1) {
    const __half h0 = __float2half_rn(f0);
    const __half h1 = __float2half_rn(f1);
    return (uint32_t)__half_as_ushort(h0) | ((uint32_t)__half_as_ushort(h1) << 16);
}
__device__ __forceinline__ void store_h4(__half* p, float4 v) {
    uint2 u;
    u.x = pack_h2(v.x, v.y);
    u.y = pack_h2(v.z, v.w);
    *reinterpret_cast<uint2*>(p) = u;
}

// ---------------------------------------------------------------------------
// Layer-1 mean aggregation (R4 shape): 128 thr/dst, 2 edge streams, 2x unroll,
// regs capped for ~full occupancy. fp16 out into A columns [256,512).
// ---------------------------------------------------------------------------
__global__ __launch_bounds__(128, 16) void agg1_kernel(const float* __restrict__ feat,
                                                       const int* __restrict__ src_idx,
                                                       const int* __restrict__ dst_idx,
                                                       __half* __restrict__ A)
{
    const int d = blockIdx.x;

    int lo = 0, hi = N_E1;
    while (lo < hi) { int mid = (lo + hi) >> 1; if (__ldg(&dst_idx[mid]) < d) lo = mid + 1; else hi = mid; }
    const int start = lo;
    hi = N_E1;
    while (lo < hi) { int mid = (lo + hi) >> 1; if (__ldg(&dst_idx[mid]) <= d) lo = mid + 1; else hi = mid; }
    const int end = lo;

    const int t    = threadIdx.x;
    const int half = t >> 6;            // 0/1 edge stream
    const int tt   = t & 63;            // float4 slice of the 256-dim row

    __shared__ float a_nb[2][256];

    float4 acc0 = make_float4(0.f, 0.f, 0.f, 0.f);
    float4 acc1 = make_float4(0.f, 0.f, 0.f, 0.f);

    int e = start + half;
    for (; e + 2 < end; e += 4) {
        const int s0 = __ldg(&src_idx[e]);
        const int s1 = __ldg(&src_idx[e + 2]);
        const float4 v0 = *reinterpret_cast<const float4*>(&feat[(size_t)s0 * 256 + tt * 4]);
        const float4 v1 = *reinterpret_cast<const float4*>(&feat[(size_t)s1 * 256 + tt * 4]);
        acc0.x += v0.x; acc0.y += v0.y; acc0.z += v0.z; acc0.w += v0.w;
        acc1.x += v1.x; acc1.y += v1.y; acc1.z += v1.z; acc1.w += v1.w;
    }
    for (; e < end; e += 2) {
        const int s = __ldg(&src_idx[e]);
        const float4 v = *reinterpret_cast<const float4*>(&feat[(size_t)s * 256 + tt * 4]);
        acc0.x += v.x; acc0.y += v.y; acc0.z += v.z; acc0.w += v.w;
    }
    acc0.x += acc1.x; acc0.y += acc1.y; acc0.z += acc1.z; acc0.w += acc1.w;
    *reinterpret_cast<float4*>(&a_nb[half][tt * 4]) = acc0;
    __syncthreads();

    if (half == 0) {
        const int deg = end - start;
        const float inv = (deg > 0) ? 1.0f / (float)deg : 0.0f;
        float4 u = *reinterpret_cast<float4*>(&a_nb[0][tt * 4]);
        const float4 w = *reinterpret_cast<float4*>(&a_nb[1][tt * 4]);
        u.x = (u.x + w.x) * inv; u.y = (u.y + w.y) * inv;
        u.z = (u.z + w.z) * inv; u.w = (u.w + w.w) * inv;
        store_h4(&A[(size_t)d * 512 + 256 + tt * 4], u);
    }
}

// ---------------------------------------------------------------------------
// Layer-2 aggregation + self copy: 1024 blocks x 64 thr.
// ---------------------------------------------------------------------------
__global__ __launch_bounds__(64) void agg2_kernel(const float* __restrict__ h,
                                                  const int* __restrict__ src_idx,
                                                  const int* __restrict__ dst_idx,
                                                  __half* __restrict__ A2)
{
    const int d = blockIdx.x;

    int lo = 0, hi = N_E2;
    while (lo < hi) { int mid = (lo + hi) >> 1; if (__ldg(&dst_idx[mid]) < d) lo = mid + 1; else hi = mid; }
    const int start = lo;
    hi = N_E2;
    while (lo < hi) { int mid = (lo + hi) >> 1; if (__ldg(&dst_idx[mid]) <= d) lo = mid + 1; else hi = mid; }
    const int end = lo;

    const int t = threadIdx.x;

    {
        const float4 v = *reinterpret_cast<const float4*>(&h[(size_t)d * 256 + t * 4]);
        store_h4(&A2[(size_t)d * 512 + t * 4], v);
    }

    float4 acc[4];
#pragma unroll
    for (int u = 0; u < 4; ++u) acc[u] = make_float4(0.f, 0.f, 0.f, 0.f);

    int e = start;
    for (; e + 3 < end; e += 4) {
        int s[4];
#pragma unroll
        for (int u = 0; u < 4; ++u) s[u] = __ldg(&src_idx[e + u]);
#pragma unroll
        for (int u = 0; u < 4; ++u) {
            const float4 v = *reinterpret_cast<const float4*>(&h[(size_t)s[u] * 256 + t * 4]);
            acc[u].x += v.x; acc[u].y += v.y; acc[u].z += v.z; acc[u].w += v.w;
        }
    }
    for (; e < end; ++e) {
        const int s = __ldg(&src_idx[e]);
        const float4 v = *reinterpret_cast<const float4*>(&h[(size_t)s * 256 + t * 4]);
        acc[0].x += v.x; acc[0].y += v.y; acc[0].z += v.z; acc[0].w += v.w;
    }
#pragma unroll
    for (int u = 1; u < 4; ++u) {
        acc[0].x += acc[u].x; acc[0].y += acc[u].y;
        acc[0].z += acc[u].z; acc[0].w += acc[u].w;
    }

    const int deg = end - start;
    const float inv = (deg > 0) ? 1.0f / (float)deg : 0.0f;
    acc[0].x *= inv; acc[0].y *= inv; acc[0].z *= inv; acc[0].w *= inv;

    store_h4(&A2[(size_t)d * 512 + 256 + t * 4], acc[0]);
}

// ---------------------------------------------------------------------------
// Convert x[:11264] into A columns [0,256) (fp16).
// ---------------------------------------------------------------------------
__global__ __launch_bounds__(256) void xcvt_kernel(const float* __restrict__ x,
                                                   __half* __restrict__ A)
{
    const int idx = blockIdx.x * 256 + threadIdx.x;
    const int r  = idx >> 6;
    const int c4 = (idx & 63) * 4;
    const float4 v = *reinterpret_cast<const float4*>(&x[(size_t)r * 256 + c4]);
    store_h4(&A[(size_t)r * 512 + c4], v);
}

// ---------------------------------------------------------------------------
// Transpose + convert W1: WT[n][k]
// ---------------------------------------------------------------------------
__global__ __launch_bounds__(256) void wcvt_kernel(const float* __restrict__ Wself,
                                                   const float* __restrict__ Wneigh,
                                                   __half* __restrict__ WT)
{
    const int idx = blockIdx.x * 256 + threadIdx.x;
    const int n = idx >> 9;
    const int k = idx & 511;
    const float v = (k < 256) ? __ldg(&Wself[(size_t)k * 256 + n])
                              : __ldg(&Wneigh[(size_t)(k - 256) * 256 + n]);
    WT[(size_t)n * 512 + k] = __float2half_rn(v);
}

// ---------------------------------------------------------------------------
// Transpose + convert W2 into padded [64][512]: cols >= 47 zero.
// ---------------------------------------------------------------------------
__global__ __launch_bounds__(256) void w2cvt_kernel(const float* __restrict__ Ws,
                                                    const float* __restrict__ Wn,
                                                    __half* __restrict__ WT2)
{
    const int idx = blockIdx.x * 256 + threadIdx.x;
    const int n = idx >> 9;
    const int k = idx & 511;
    float v = 0.f;
    if (n < C_DIM)
        v = (k < 256) ? __ldg(&Ws[(size_t)k * C_DIM + n])
                      : __ldg(&Wn[(size_t)(k - 256) * C_DIM + n]);
    WT2[(size_t)n * 512 + k] = __float2half_rn(v);
}

// ---------------------------------------------------------------------------
// cp.async / ldmatrix helpers
// ---------------------------------------------------------------------------
__device__ __forceinline__ void cp_async16(uint32_t saddr, const void* g) {
    asm volatile("cp.async.ca.shared.global [%0], [%1], 16;\n" :: "r"(saddr), "l"(g));
}
__device__ __forceinline__ void cp_commit() {
    asm volatile("cp.async.commit_group;\n" ::: "memory");
}
__device__ __forceinline__ void ldsm_x4(uint32_t& r0, uint32_t& r1, uint32_t& r2, uint32_t& r3,
                                        uint32_t addr) {
    asm volatile("ldmatrix.sync.aligned.m8n8.x4.shared.b16 {%0,%1,%2,%3}, [%4];\n"
                 : "=r"(r0), "=r"(r1), "=r"(r2), "=r"(r3) : "r"(addr));
}
__device__ __forceinline__ void mma_f16(float c[4], const uint32_t a[4], const uint32_t b[2]) {
    asm volatile(
        "mma.sync.aligned.m16n8k16.row.col.f32.f16.f16.f32 "
        "{%0,%1,%2,%3}, {%4,%5,%6,%7}, {%8,%9}, {%0,%1,%2,%3};\n"
        : "+f"(c[0]), "+f"(c[1]), "+f"(c[2]), "+f"(c[3])
        : "r"(a[0]), "r"(a[1]), "r"(a[2]), "r"(a[3]), "r"(b[0]), "r"(b[1]));
}

// ---------------------------------------------------------------------------
// Shared fp16 MMA mainloop (CTA 128x64, BK=32, 3-stage cp.async ring).
// ---------------------------------------------------------------------------
#define G1_BM 128
#define G1_BN 64
#define G1_BK 32
#define SRW 20
#define OFF_A 0
#define OFF_B (G1_BM * SRW)
#define STAGE_WORDS ((G1_BM + G1_BN) * SRW)
#define N_KTILES 16

struct MmaCtx {
    float acc[2][4][4];
    int wm, wn, g, tg;
};

__device__ __forceinline__ void run_mma_tile(
    const __half* __restrict__ Abase,
    const __half* __restrict__ Bbase,
    uint32_t* smem, MmaCtx& ctx)
{
    const int tid  = threadIdx.x;
    const int warp = tid >> 5;
    const int lane = tid & 31;
    ctx.wm = warp >> 1;
    ctx.wn = warp & 1;
    ctx.g  = lane >> 2;
    ctx.tg = lane & 3;

    uint32_t sbase;
    asm("{ .reg .u64 t; cvta.to.shared.u64 t, %1; cvt.u32.u64 %0, t; }"
        : "=r"(sbase) : "l"(smem));

    const int a_row0 = tid >> 2;
    const int a_ch   = tid & 3;

    const __half* gA0 = Abase + (size_t)a_row0 * 512 + a_ch * 8;
    const __half* gA1 = Abase + (size_t)(a_row0 + 64) * 512 + a_ch * 8;
    const __half* gB  = Bbase + (size_t)a_row0 * 512 + a_ch * 8;

    const uint32_t sA0 = sbase + (OFF_A + a_row0 * SRW + a_ch * 4) * 4;
    const uint32_t sA1 = sbase + (OFF_A + (a_row0 + 64) * SRW + a_ch * 4) * 4;
    const uint32_t sB  = sbase + (OFF_B + a_row0 * SRW + a_ch * 4) * 4;

    uint32_t aAddr[2];
#pragma unroll
    for (int i = 0; i < 2; ++i) {
        const int row = ctx.wm * 32 + i * 16 + (lane & 15);
        const int word = (lane >> 4) * 4;
        aAddr[i] = sbase + (OFF_A + row * SRW + word) * 4;
    }
    uint32_t bAddr[2];
#pragma unroll
    for (int p = 0; p < 2; ++p) {
        const int row = ctx.wn * 32 + p * 16 + (lane & 7) + ((lane >> 4) << 3);
        const int word = ((lane >> 3) & 1) * 4;
        bAddr[p] = sbase + (OFF_B + row * SRW + word) * 4;
    }
    const uint32_t stage_bytes = STAGE_WORDS * 4;

#pragma unroll
    for (int i = 0; i < 2; ++i)
#pragma unroll
        for (int j = 0; j < 4; ++j)
#pragma unroll
            for (int r = 0; r < 4; ++r) ctx.acc[i][j][r] = 0.f;

#pragma unroll
    for (int pt = 0; pt < 2; ++pt) {
        const uint32_t so = pt * stage_bytes;
        const int kn = pt * G1_BK;
        cp_async16(sA0 + so, gA0 + kn);
        cp_async16(sA1 + so, gA1 + kn);
        cp_async16(sB + so,  gB + kn);
        cp_commit();
    }

    int stage = 0;
    for (int t = 0; t < N_KTILES; ++t) {
        if (t + 1 < N_KTILES)
            asm volatile("cp.async.wait_group 1;" ::: "memory");
        else
            asm volatile("cp.async.wait_group 0;" ::: "memory");
        __syncthreads();

        if (t + 2 < N_KTILES) {
            const int kn = (t + 2) * G1_BK;
            const uint32_t so = ((stage + 2) % 3) * stage_bytes;
            cp_async16(sA0 + so, gA0 + kn);
            cp_async16(sA1 + so, gA1 + kn);
            cp_async16(sB + so,  gB + kn);
            cp_commit();
        }

        const uint32_t so = stage * stage_bytes;
#pragma unroll
        for (int s = 0; s < 2; ++s) {
            const uint32_t ko = so + s * 32;
            uint32_t Af[2][4], Bf[2][4];
#pragma unroll
            for (int i = 0; i < 2; ++i)
                ldsm_x4(Af[i][0], Af[i][1], Af[i][2], Af[i][3], aAddr[i] + ko);
#pragma unroll
            for (int p = 0; p < 2; ++p)
                ldsm_x4(Bf[p][0], Bf[p][1], Bf[p][2], Bf[p][3], bAddr[p] + ko);
#pragma unroll
            for (int i = 0; i < 2; ++i)
#pragma unroll
                for (int j = 0; j < 4; ++j) {
                    const uint32_t bf[2] = { Bf[j >> 1][(j & 1) * 2], Bf[j >> 1][(j & 1) * 2 + 1] };
                    mma_f16(ctx.acc[i][j], Af[i], bf);
                }
        }
        stage = (stage + 1) % 3;
    }
}

// ---------------------------------------------------------------------------
// Layer-1 GEMM: h = relu(A @ WT^T + b1)
// ---------------------------------------------------------------------------
__global__ __launch_bounds__(256) void gemm1_kernel(
    const __half* __restrict__ A,
    const __half* __restrict__ WT,
    const float* __restrict__ bias,
    float* __restrict__ out)
{
    __shared__ __align__(16) uint32_t smem[3 * STAGE_WORDS];
    const int bx = blockIdx.x;
    const int by = blockIdx.y;

    MmaCtx ctx;
    run_mma_tile(A + (size_t)(by * G1_BM) * 512, WT + (size_t)(bx * G1_BN) * 512, smem, ctx);

#pragma unroll
    for (int i = 0; i < 2; ++i) {
#pragma unroll
        for (int j = 0; j < 4; ++j) {
            const int col = bx * G1_BN + ctx.wn * 32 + j * 8 + ctx.tg * 2;
            const float b0 = __ldg(&bias[col]);
            const float b1 = __ldg(&bias[col + 1]);
            const int r0 = by * G1_BM + ctx.wm * 32 + i * 16 + ctx.g;
            float2 v0;
            v0.x = fmaxf(ctx.acc[i][j][0] + b0, 0.f);
            v0.y = fmaxf(ctx.acc[i][j][1] + b1, 0.f);
            *reinterpret_cast<float2*>(&out[(size_t)r0 * 256 + col]) = v0;
            float2 v1;
            v1.x = fmaxf(ctx.acc[i][j][2] + b0, 0.f);
            v1.y = fmaxf(ctx.acc[i][j][3] + b1, 0.f);
            *reinterpret_cast<float2*>(&out[(size_t)(r0 + 8) * 256 + col]) = v1;
        }
    }
}

// ---------------------------------------------------------------------------
// Layer-2 GEMM: out = A2 @ WT2^T + b2 (no relu), cols >= 47 dropped.
// ---------------------------------------------------------------------------
__global__ __launch_bounds__(256) void gemm2_tc_kernel(
    const __half* __restrict__ A2,
    const __half* __restrict__ WT2,
    const float* __restrict__ bias,
    float* __restrict__ out)
{
    __shared__ __align__(16) uint32_t smem[3 * STAGE_WORDS];
    const int by = blockIdx.x;

    MmaCtx ctx;
    run_mma_tile(A2 + (size_t)(by * G1_BM) * 512, WT2, smem, ctx);

#pragma unroll
    for (int i = 0; i < 2; ++i) {
#pragma unroll
        for (int j = 0; j < 4; ++j) {
            const int col = ctx.wn * 32 + j * 8 + ctx.tg * 2;
            const int r0 = by * G1_BM + ctx.wm * 32 + i * 16 + ctx.g;
            if (col < C_DIM) {
                const float b0 = __ldg(&bias[col]);
                out[(size_t)r0 * C_DIM + col]       = ctx.acc[i][j][0] + b0;
                out[(size_t)(r0 + 8) * C_DIM + col] = ctx.acc[i][j][2] + b0;
            }
            if (col + 1 < C_DIM) {
                const float b1 = __ldg(&bias[col + 1]);
                out[(size_t)r0 * C_DIM + col + 1]       = ctx.acc[i][j][1] + b1;
                out[(size_t)(r0 + 8) * C_DIM + col + 1] = ctx.acc[i][j][3] + b1;
            }
        }
    }
}

// ---------------------------------------------------------------------------
// Launch
// ---------------------------------------------------------------------------
extern "C" void kernel_launch(void* const* d_in, const int* in_sizes, int n_in,
                              void* d_out, int out_size)
{
    const float* x       = (const float*)d_in[0];
    const int*   src1    = (const int*)  d_in[1];
    const int*   dst1    = (const int*)  d_in[2];
    const int*   src2    = (const int*)  d_in[3];
    const int*   dst2    = (const int*)  d_in[4];
    const float* Wself1  = (const float*)d_in[5];
    const float* Wneigh1 = (const float*)d_in[6];
    const float* b1      = (const float*)d_in[7];
    const float* Wself2  = (const float*)d_in[8];
    const float* Wneigh2 = (const float*)d_in[9];
    const float* b2      = (const float*)d_in[10];
    float* out = (float*)d_out;

    __half *A, *WT, *A2, *WT2;
    float* hbuf;
    cudaGetSymbolAddress((void**)&A,   g_A);
    cudaGetSymbolAddress((void**)&WT,  g_WT);
    cudaGetSymbolAddress((void**)&A2,  g_A2);
    cudaGetSymbolAddress((void**)&WT2, g_WT2);
    cudaGetSymbolAddress((void**)&hbuf, g_h);

    // Prep
    wcvt_kernel<<<(256 * 512) / 256, 256>>>(Wself1, Wneigh1, WT);
    w2cvt_kernel<<<(64 * 512) / 256, 256>>>(Wself2, Wneigh2, WT2);
    xcvt_kernel<<<(N_DST1 * 64) / 256, 256>>>(x, A);
    agg1_kernel<<<N_DST1, 128>>>(x, src1, dst1, A);

    // Layer 1 GEMM + bias + relu
    dim3 g1(H_DIM / G1_BN, N_DST1 / G1_BM);   // (4, 88)
    gemm1_kernel<<<g1, 256>>>(A, WT, b1, hbuf);

    // Layer 2: aggregate + GEMM
    agg2_kernel<<<N_DST2, 64>>>(hbuf, src2, dst2, A2);
    gemm2_tc_kernel<<<N_DST2 / G1_BM, 256>>>(A2, WT2, b2, out);
}

// round 13
// speedup vs baseline: 1.3030x; 1.0226x over previous
#include <cuda_runtime.h>
#include <cuda_fp16.h>
#include <cstdint>

// Problem constants
#define N_SRC1  292864
#define N_DST1  11264
#define N_E1    281600
#define N_DST2  1024
#define N_E2    10240
#define IN_DIM  256
#define H_DIM   256
#define C_DIM   47

// Scratch (device globals — no allocation allowed)
__device__ __half g_A[N_DST1 * 512];      // [x_dst | hneigh1] fp16
__device__ __half g_WT[256 * 512];        // [Wself1;Wneigh1]^T fp16
__device__ float  g_h[N_DST1 * H_DIM];    // relu(layer-1 out) fp32
__device__ __half g_A2[N_DST2 * 512];     // [h_dst | hneigh2] fp16
__device__ __half g_WT2[64 * 512];        // [Wself2;Wneigh2]^T fp16, cols 47-63 zero

// ---------------------------------------------------------------------------
// fp16 helpers
// ---------------------------------------------------------------------------
__device__ __forceinline__ uint32_t pack_h2(float f0, float f1) {
    const __half h0 = __float2half_rn(f0);
    const __half h1 = __float2half_rn(f1);
    return (uint32_t)__half_as_ushort(h0) | ((uint32_t)__half_as_ushort(h1) << 16);
}
__device__ __forceinline__ void store_h4(__half* p, float4 v) {
    uint2 u;
    u.x = pack_h2(v.x, v.y);
    u.y = pack_h2(v.z, v.w);
    *reinterpret_cast<uint2*>(p) = u;
}

// ---------------------------------------------------------------------------
// Layer-1 mean aggregation + self-row convert (fused xcvt):
// 128 thr/dst, 2 edge streams, 2x unroll, regs capped for full occupancy.
// A[d][0:256)   = fp16(x[d])
// A[d][256:512) = fp16(mean of gathered x rows)
// ---------------------------------------------------------------------------
__global__ __launch_bounds__(128, 16) void agg1_kernel(const float* __restrict__ feat,
                                                       const int* __restrict__ src_idx,
                                                       const int* __restrict__ dst_idx,
                                                       __half* __restrict__ A)
{
    const int d = blockIdx.x;

    int lo = 0, hi = N_E1;
    while (lo < hi) { int mid = (lo + hi) >> 1; if (__ldg(&dst_idx[mid]) < d) lo = mid + 1; else hi = mid; }
    const int start = lo;
    hi = N_E1;
    while (lo < hi) { int mid = (lo + hi) >> 1; if (__ldg(&dst_idx[mid]) <= d) lo = mid + 1; else hi = mid; }
    const int end = lo;

    const int t    = threadIdx.x;
    const int half = t >> 6;            // 0/1 edge stream
    const int tt   = t & 63;            // float4 slice of the 256-dim row

    __shared__ float a_nb[2][256];

    float4 acc0 = make_float4(0.f, 0.f, 0.f, 0.f);
    float4 acc1 = make_float4(0.f, 0.f, 0.f, 0.f);

    int e = start + half;
    for (; e + 2 < end; e += 4) {
        const int s0 = __ldg(&src_idx[e]);
        const int s1 = __ldg(&src_idx[e + 2]);
        const float4 v0 = *reinterpret_cast<const float4*>(&feat[(size_t)s0 * 256 + tt * 4]);
        const float4 v1 = *reinterpret_cast<const float4*>(&feat[(size_t)s1 * 256 + tt * 4]);
        acc0.x += v0.x; acc0.y += v0.y; acc0.z += v0.z; acc0.w += v0.w;
        acc1.x += v1.x; acc1.y += v1.y; acc1.z += v1.z; acc1.w += v1.w;
    }
    for (; e < end; e += 2) {
        const int s = __ldg(&src_idx[e]);
        const float4 v = *reinterpret_cast<const float4*>(&feat[(size_t)s * 256 + tt * 4]);
        acc0.x += v.x; acc0.y += v.y; acc0.z += v.z; acc0.w += v.w;
    }
    acc0.x += acc1.x; acc0.y += acc1.y; acc0.z += acc1.z; acc0.w += acc1.w;
    *reinterpret_cast<float4*>(&a_nb[half][tt * 4]) = acc0;

    // fused xcvt: stream-1 threads convert the self row while stream-0 reduces
    if (half == 1) {
        const float4 v = *reinterpret_cast<const float4*>(&feat[(size_t)d * 256 + tt * 4]);
        store_h4(&A[(size_t)d * 512 + tt * 4], v);
    }
    __syncthreads();

    if (half == 0) {
        const int deg = end - start;
        const float inv = (deg > 0) ? 1.0f / (float)deg : 0.0f;
        float4 u = *reinterpret_cast<float4*>(&a_nb[0][tt * 4]);
        const float4 w = *reinterpret_cast<float4*>(&a_nb[1][tt * 4]);
        u.x = (u.x + w.x) * inv; u.y = (u.y + w.y) * inv;
        u.z = (u.z + w.z) * inv; u.w = (u.w + w.w) * inv;
        store_h4(&A[(size_t)d * 512 + 256 + tt * 4], u);
    }
}

// ---------------------------------------------------------------------------
// Layer-2 aggregation + self copy: 1024 blocks x 64 thr.
// ---------------------------------------------------------------------------
__global__ __launch_bounds__(64) void agg2_kernel(const float* __restrict__ h,
                                                  const int* __restrict__ src_idx,
                                                  const int* __restrict__ dst_idx,
                                                  __half* __restrict__ A2)
{
    const int d = blockIdx.x;

    int lo = 0, hi = N_E2;
    while (lo < hi) { int mid = (lo + hi) >> 1; if (__ldg(&dst_idx[mid]) < d) lo = mid + 1; else hi = mid; }
    const int start = lo;
    hi = N_E2;
    while (lo < hi) { int mid = (lo + hi) >> 1; if (__ldg(&dst_idx[mid]) <= d) lo = mid + 1; else hi = mid; }
    const int end = lo;

    const int t = threadIdx.x;

    {
        const float4 v = *reinterpret_cast<const float4*>(&h[(size_t)d * 256 + t * 4]);
        store_h4(&A2[(size_t)d * 512 + t * 4], v);
    }

    float4 acc[4];
#pragma unroll
    for (int u = 0; u < 4; ++u) acc[u] = make_float4(0.f, 0.f, 0.f, 0.f);

    int e = start;
    for (; e + 3 < end; e += 4) {
        int s[4];
#pragma unroll
        for (int u = 0; u < 4; ++u) s[u] = __ldg(&src_idx[e + u]);
#pragma unroll
        for (int u = 0; u < 4; ++u) {
            const float4 v = *reinterpret_cast<const float4*>(&h[(size_t)s[u] * 256 + t * 4]);
            acc[u].x += v.x; acc[u].y += v.y; acc[u].z += v.z; acc[u].w += v.w;
        }
    }
    for (; e < end; ++e) {
        const int s = __ldg(&src_idx[e]);
        const float4 v = *reinterpret_cast<const float4*>(&h[(size_t)s * 256 + t * 4]);
        acc[0].x += v.x; acc[0].y += v.y; acc[0].z += v.z; acc[0].w += v.w;
    }
#pragma unroll
    for (int u = 1; u < 4; ++u) {
        acc[0].x += acc[u].x; acc[0].y += acc[u].y;
        acc[0].z += acc[u].z; acc[0].w += acc[u].w;
    }

    const int deg = end - start;
    const float inv = (deg > 0) ? 1.0f / (float)deg : 0.0f;
    acc[0].x *= inv; acc[0].y *= inv; acc[0].z *= inv; acc[0].w *= inv;

    store_h4(&A2[(size_t)d * 512 + 256 + t * 4], acc[0]);
}

// ---------------------------------------------------------------------------
// Merged weight transpose+convert:
// idx in [0, 256*512)        -> WT[n][k]  from W1
// idx in [256*512, 320*512)  -> WT2[n][k] from W2 (cols >= 47 zero)
// ---------------------------------------------------------------------------
__global__ __launch_bounds__(256) void wcvt_all_kernel(const float* __restrict__ Wself1,
                                                       const float* __restrict__ Wneigh1,
                                                       const float* __restrict__ Ws2,
                                                       const float* __restrict__ Wn2,
                                                       __half* __restrict__ WT,
                                                       __half* __restrict__ WT2)
{
    const int idx = blockIdx.x * 256 + threadIdx.x;
    if (idx < 256 * 512) {
        const int n = idx >> 9;
        const int k = idx & 511;
        const float v = (k < 256) ? __ldg(&Wself1[(size_t)k * 256 + n])
                                  : __ldg(&Wneigh1[(size_t)(k - 256) * 256 + n]);
        WT[(size_t)n * 512 + k] = __float2half_rn(v);
    } else {
        const int j = idx - 256 * 512;
        const int n = j >> 9;
        const int k = j & 511;
        float v = 0.f;
        if (n < C_DIM)
            v = (k < 256) ? __ldg(&Ws2[(size_t)k * C_DIM + n])
                          : __ldg(&Wn2[(size_t)(k - 256) * C_DIM + n]);
        WT2[(size_t)n * 512 + k] = __float2half_rn(v);
    }
}

// ---------------------------------------------------------------------------
// cp.async / ldmatrix helpers
// ---------------------------------------------------------------------------
__device__ __forceinline__ void cp_async16(uint32_t saddr, const void* g) {
    asm volatile("cp.async.ca.shared.global [%0], [%1], 16;\n" :: "r"(saddr), "l"(g));
}
__device__ __forceinline__ void cp_commit() {
    asm volatile("cp.async.commit_group;\n" ::: "memory");
}
__device__ __forceinline__ void ldsm_x4(uint32_t& r0, uint32_t& r1, uint32_t& r2, uint32_t& r3,
                                        uint32_t addr) {
    asm volatile("ldmatrix.sync.aligned.m8n8.x4.shared.b16 {%0,%1,%2,%3}, [%4];\n"
                 : "=r"(r0), "=r"(r1), "=r"(r2), "=r"(r3) : "r"(addr));
}
__device__ __forceinline__ void mma_f16(float c[4], const uint32_t a[4], const uint32_t b[2]) {
    asm volatile(
        "mma.sync.aligned.m16n8k16.row.col.f32.f16.f16.f32 "
        "{%0,%1,%2,%3}, {%4,%5,%6,%7}, {%8,%9}, {%0,%1,%2,%3};\n"
        : "+f"(c[0]), "+f"(c[1]), "+f"(c[2]), "+f"(c[3])
        : "r"(a[0]), "r"(a[1]), "r"(a[2]), "r"(a[3]), "r"(b[0]), "r"(b[1]));
}

// ---------------------------------------------------------------------------
// Shared fp16 MMA mainloop (CTA 128x64, BK=32, 3-stage cp.async ring).
// ---------------------------------------------------------------------------
#define G1_BM 128
#define G1_BN 64
#define G1_BK 32
#define SRW 20
#define OFF_A 0
#define OFF_B (G1_BM * SRW)
#define STAGE_WORDS ((G1_BM + G1_BN) * SRW)
#define N_KTILES 16

struct MmaCtx {
    float acc[2][4][4];
    int wm, wn, g, tg;
};

__device__ __forceinline__ void run_mma_tile(
    const __half* __restrict__ Abase,
    const __half* __restrict__ Bbase,
    uint32_t* smem, MmaCtx& ctx)
{
    const int tid  = threadIdx.x;
    const int warp = tid >> 5;
    const int lane = tid & 31;
    ctx.wm = warp >> 1;
    ctx.wn = warp & 1;
    ctx.g  = lane >> 2;
    ctx.tg = lane & 3;

    uint32_t sbase;
    asm("{ .reg .u64 t; cvta.to.shared.u64 t, %1; cvt.u32.u64 %0, t; }"
        : "=r"(sbase) : "l"(smem));

    const int a_row0 = tid >> 2;
    const int a_ch   = tid & 3;

    const __half* gA0 = Abase + (size_t)a_row0 * 512 + a_ch * 8;
    const __half* gA1 = Abase + (size_t)(a_row0 + 64) * 512 + a_ch * 8;
    const __half* gB  = Bbase + (size_t)a_row0 * 512 + a_ch * 8;

    const uint32_t sA0 = sbase + (OFF_A + a_row0 * SRW + a_ch * 4) * 4;
    const uint32_t sA1 = sbase + (OFF_A + (a_row0 + 64) * SRW + a_ch * 4) * 4;
    const uint32_t sB  = sbase + (OFF_B + a_row0 * SRW + a_ch * 4) * 4;

    uint32_t aAddr[2];
#pragma unroll
    for (int i = 0; i < 2; ++i) {
        const int row = ctx.wm * 32 + i * 16 + (lane & 15);
        const int word = (lane >> 4) * 4;
        aAddr[i] = sbase + (OFF_A + row * SRW + word) * 4;
    }
    uint32_t bAddr[2];
#pragma unroll
    for (int p = 0; p < 2; ++p) {
        const int row = ctx.wn * 32 + p * 16 + (lane & 7) + ((lane >> 4) << 3);
        const int word = ((lane >> 3) & 1) * 4;
        bAddr[p] = sbase + (OFF_B + row * SRW + word) * 4;
    }
    const uint32_t stage_bytes = STAGE_WORDS * 4;

#pragma unroll
    for (int i = 0; i < 2; ++i)
#pragma unroll
        for (int j = 0; j < 4; ++j)
#pragma unroll
            for (int r = 0; r < 4; ++r) ctx.acc[i][j][r] = 0.f;

#pragma unroll
    for (int pt = 0; pt < 2; ++pt) {
        const uint32_t so = pt * stage_bytes;
        const int kn = pt * G1_BK;
        cp_async16(sA0 + so, gA0 + kn);
        cp_async16(sA1 + so, gA1 + kn);
        cp_async16(sB + so,  gB + kn);
        cp_commit();
    }

    int stage = 0;
    for (int t = 0; t < N_KTILES; ++t) {
        if (t + 1 < N_KTILES)
            asm volatile("cp.async.wait_group 1;" ::: "memory");
        else
            asm volatile("cp.async.wait_group 0;" ::: "memory");
        __syncthreads();

        if (t + 2 < N_KTILES) {
            const int kn = (t + 2) * G1_BK;
            const uint32_t so = ((stage + 2) % 3) * stage_bytes;
            cp_async16(sA0 + so, gA0 + kn);
            cp_async16(sA1 + so, gA1 + kn);
            cp_async16(sB + so,  gB + kn);
            cp_commit();
        }

        const uint32_t so = stage * stage_bytes;
#pragma unroll
        for (int s = 0; s < 2; ++s) {
            const uint32_t ko = so + s * 32;
            uint32_t Af[2][4], Bf[2][4];
#pragma unroll
            for (int i = 0; i < 2; ++i)
                ldsm_x4(Af[i][0], Af[i][1], Af[i][2], Af[i][3], aAddr[i] + ko);
#pragma unroll
            for (int p = 0; p < 2; ++p)
                ldsm_x4(Bf[p][0], Bf[p][1], Bf[p][2], Bf[p][3], bAddr[p] + ko);
#pragma unroll
            for (int i = 0; i < 2; ++i)
#pragma unroll
                for (int j = 0; j < 4; ++j) {
                    const uint32_t bf[2] = { Bf[j >> 1][(j & 1) * 2], Bf[j >> 1][(j & 1) * 2 + 1] };
                    mma_f16(ctx.acc[i][j], Af[i], bf);
                }
        }
        stage = (stage + 1) % 3;
    }
}

// ---------------------------------------------------------------------------
// Layer-1 GEMM: h = relu(A @ WT^T + b1)
// ---------------------------------------------------------------------------
__global__ __launch_bounds__(256) void gemm1_kernel(
    const __half* __restrict__ A,
    const __half* __restrict__ WT,
    const float* __restrict__ bias,
    float* __restrict__ out)
{
    __shared__ __align__(16) uint32_t smem[3 * STAGE_WORDS];
    const int bx = blockIdx.x;
    const int by = blockIdx.y;

    MmaCtx ctx;
    run_mma_tile(A + (size_t)(by * G1_BM) * 512, WT + (size_t)(bx * G1_BN) * 512, smem, ctx);

#pragma unroll
    for (int i = 0; i < 2; ++i) {
#pragma unroll
        for (int j = 0; j < 4; ++j) {
            const int col = bx * G1_BN + ctx.wn * 32 + j * 8 + ctx.tg * 2;
            const float b0 = __ldg(&bias[col]);
            const float b1 = __ldg(&bias[col + 1]);
            const int r0 = by * G1_BM + ctx.wm * 32 + i * 16 + ctx.g;
            float2 v0;
            v0.x = fmaxf(ctx.acc[i][j][0] + b0, 0.f);
            v0.y = fmaxf(ctx.acc[i][j][1] + b1, 0.f);
            *reinterpret_cast<float2*>(&out[(size_t)r0 * 256 + col]) = v0;
            float2 v1;
            v1.x = fmaxf(ctx.acc[i][j][2] + b0, 0.f);
            v1.y = fmaxf(ctx.acc[i][j][3] + b1, 0.f);
            *reinterpret_cast<float2*>(&out[(size_t)(r0 + 8) * 256 + col]) = v1;
        }
    }
}

// ---------------------------------------------------------------------------
// Layer-2 GEMM: out = A2 @ WT2^T + b2 (no relu), cols >= 47 dropped.
// ---------------------------------------------------------------------------
__global__ __launch_bounds__(256) void gemm2_tc_kernel(
    const __half* __restrict__ A2,
    const __half* __restrict__ WT2,
    const float* __restrict__ bias,
    float* __restrict__ out)
{
    __shared__ __align__(16) uint32_t smem[3 * STAGE_WORDS];
    const int by = blockIdx.x;

    MmaCtx ctx;
    run_mma_tile(A2 + (size_t)(by * G1_BM) * 512, WT2, smem, ctx);

#pragma unroll
    for (int i = 0; i < 2; ++i) {
#pragma unroll
        for (int j = 0; j < 4; ++j) {
            const int col = ctx.wn * 32 + j * 8 + ctx.tg * 2;
            const int r0 = by * G1_BM + ctx.wm * 32 + i * 16 + ctx.g;
            if (col < C_DIM) {
                const float b0 = __ldg(&bias[col]);
                out[(size_t)r0 * C_DIM + col]       = ctx.acc[i][j][0] + b0;
                out[(size_t)(r0 + 8) * C_DIM + col] = ctx.acc[i][j][2] + b0;
            }
            if (col + 1 < C_DIM) {
                const float b1 = __ldg(&bias[col + 1]);
                out[(size_t)r0 * C_DIM + col + 1]       = ctx.acc[i][j][1] + b1;
                out[(size_t)(r0 + 8) * C_DIM + col + 1] = ctx.acc[i][j][3] + b1;
            }
        }
    }
}

// ---------------------------------------------------------------------------
// Launch
// ---------------------------------------------------------------------------
extern "C" void kernel_launch(void* const* d_in, const int* in_sizes, int n_in,
                              void* d_out, int out_size)
{
    const float* x       = (const float*)d_in[0];
    const int*   src1    = (const int*)  d_in[1];
    const int*   dst1    = (const int*)  d_in[2];
    const int*   src2    = (const int*)  d_in[3];
    const int*   dst2    = (const int*)  d_in[4];
    const float* Wself1  = (const float*)d_in[5];
    const float* Wneigh1 = (const float*)d_in[6];
    const float* b1      = (const float*)d_in[7];
    const float* Wself2  = (const float*)d_in[8];
    const float* Wneigh2 = (const float*)d_in[9];
    const float* b2      = (const float*)d_in[10];
    float* out = (float*)d_out;

    __half *A, *WT, *A2, *WT2;
    float* hbuf;
    cudaGetSymbolAddress((void**)&A,   g_A);
    cudaGetSymbolAddress((void**)&WT,  g_WT);
    cudaGetSymbolAddress((void**)&A2,  g_A2);
    cudaGetSymbolAddress((void**)&WT2, g_WT2);
    cudaGetSymbolAddress((void**)&hbuf, g_h);

    // Prep: merged weight transpose+convert (both layers)
    wcvt_all_kernel<<<(320 * 512) / 256, 256>>>(Wself1, Wneigh1, Wself2, Wneigh2, WT, WT2);

    // Layer 1: aggregation + fused x convert
    agg1_kernel<<<N_DST1, 128>>>(x, src1, dst1, A);

    // Layer 1 GEMM + bias + relu
    dim3 g1(H_DIM / G1_BN, N_DST1 / G1_BM);   // (4, 88)
    gemm1_kernel<<<g1, 256>>>(A, WT, b1, hbuf);

    // Layer 2: aggregate + GEMM
    agg2_kernel<<<N_DST2, 64>>>(hbuf, src2, dst2, A2);
    gemm2_tc_kernel<<<N_DST2 / G1_BM, 256>>>(A2, WT2, b2, out);
}

// round 14
// speedup vs baseline: 1.3085x; 1.0043x over previous
#include <cuda_runtime.h>
#include <cuda_fp16.h>
#include <cstdint>

// Problem constants
#define N_SRC1  292864
#define N_DST1  11264
#define N_E1    281600
#define N_DST2  1024
#define N_E2    10240
#define IN_DIM  256
#define H_DIM   256
#define C_DIM   47

// Scratch (device globals — no allocation allowed)
__device__ __half g_A[N_DST1 * 512];      // [x_dst | hneigh1] fp16
__device__ __half g_WT[256 * 512];        // [Wself1;Wneigh1]^T fp16
__device__ float  g_h[N_DST1 * H_DIM];    // relu(layer-1 out) fp32
__device__ __half g_A2[N_DST2 * 512];     // [h_dst | hneigh2] fp16
__device__ __half g_WT2[64 * 512];        // [Wself2;Wneigh2]^T fp16, cols 47-63 zero

// ---------------------------------------------------------------------------
// fp16 helpers
// ---------------------------------------------------------------------------
__device__ __forceinline__ uint32_t pack_h2(float f0, float f1) {
    const __half h0 = __float2half_rn(f0);
    const __half h1 = __float2half_rn(f1);
    return (uint32_t)__half_as_ushort(h0) | ((uint32_t)__half_as_ushort(h1) << 16);
}
__device__ __forceinline__ void store_h4(__half* p, float4 v) {
    uint2 u;
    u.x = pack_h2(v.x, v.y);
    u.y = pack_h2(v.z, v.w);
    *reinterpret_cast<uint2*>(p) = u;
}

// ---------------------------------------------------------------------------
// Layer-1 mean aggregation + self-row convert (fused xcvt):
// 128 thr/dst, 2 edge streams, 2x unroll, regs capped for full occupancy.
// ---------------------------------------------------------------------------
__global__ __launch_bounds__(128, 16) void agg1_kernel(const float* __restrict__ feat,
                                                       const int* __restrict__ src_idx,
                                                       const int* __restrict__ dst_idx,
                                                       __half* __restrict__ A)
{
    const int d = blockIdx.x;

    int lo = 0, hi = N_E1;
    while (lo < hi) { int mid = (lo + hi) >> 1; if (__ldg(&dst_idx[mid]) < d) lo = mid + 1; else hi = mid; }
    const int start = lo;
    hi = N_E1;
    while (lo < hi) { int mid = (lo + hi) >> 1; if (__ldg(&dst_idx[mid]) <= d) lo = mid + 1; else hi = mid; }
    const int end = lo;

    const int t    = threadIdx.x;
    const int half = t >> 6;            // 0/1 edge stream
    const int tt   = t & 63;            // float4 slice of the 256-dim row

    __shared__ float a_nb[2][256];

    float4 acc0 = make_float4(0.f, 0.f, 0.f, 0.f);
    float4 acc1 = make_float4(0.f, 0.f, 0.f, 0.f);

    int e = start + half;
    for (; e + 2 < end; e += 4) {
        const int s0 = __ldg(&src_idx[e]);
        const int s1 = __ldg(&src_idx[e + 2]);
        const float4 v0 = *reinterpret_cast<const float4*>(&feat[(size_t)s0 * 256 + tt * 4]);
        const float4 v1 = *reinterpret_cast<const float4*>(&feat[(size_t)s1 * 256 + tt * 4]);
        acc0.x += v0.x; acc0.y += v0.y; acc0.z += v0.z; acc0.w += v0.w;
        acc1.x += v1.x; acc1.y += v1.y; acc1.z += v1.z; acc1.w += v1.w;
    }
    for (; e < end; e += 2) {
        const int s = __ldg(&src_idx[e]);
        const float4 v = *reinterpret_cast<const float4*>(&feat[(size_t)s * 256 + tt * 4]);
        acc0.x += v.x; acc0.y += v.y; acc0.z += v.z; acc0.w += v.w;
    }
    acc0.x += acc1.x; acc0.y += acc1.y; acc0.z += acc1.z; acc0.w += acc1.w;
    *reinterpret_cast<float4*>(&a_nb[half][tt * 4]) = acc0;

    // fused xcvt: stream-1 threads convert the self row while stream-0 reduces
    if (half == 1) {
        const float4 v = *reinterpret_cast<const float4*>(&feat[(size_t)d * 256 + tt * 4]);
        store_h4(&A[(size_t)d * 512 + tt * 4], v);
    }
    __syncthreads();

    if (half == 0) {
        const int deg = end - start;
        const float inv = (deg > 0) ? 1.0f / (float)deg : 0.0f;
        float4 u = *reinterpret_cast<float4*>(&a_nb[0][tt * 4]);
        const float4 w = *reinterpret_cast<float4*>(&a_nb[1][tt * 4]);
        u.x = (u.x + w.x) * inv; u.y = (u.y + w.y) * inv;
        u.z = (u.z + w.z) * inv; u.w = (u.w + w.w) * inv;
        store_h4(&A[(size_t)d * 512 + 256 + tt * 4], u);
    }
}

// ---------------------------------------------------------------------------
// Layer-2 aggregation + self copy (agg1 recipe): 1024 blocks x 128 thr,
// 2 edge streams, self-copy overlapped on stream 1, regs capped.
// ---------------------------------------------------------------------------
__global__ __launch_bounds__(128, 16) void agg2_kernel(const float* __restrict__ h,
                                                       const int* __restrict__ src_idx,
                                                       const int* __restrict__ dst_idx,
                                                       __half* __restrict__ A2)
{
    const int d = blockIdx.x;

    int lo = 0, hi = N_E2;
    while (lo < hi) { int mid = (lo + hi) >> 1; if (__ldg(&dst_idx[mid]) < d) lo = mid + 1; else hi = mid; }
    const int start = lo;
    hi = N_E2;
    while (lo < hi) { int mid = (lo + hi) >> 1; if (__ldg(&dst_idx[mid]) <= d) lo = mid + 1; else hi = mid; }
    const int end = lo;

    const int t    = threadIdx.x;
    const int half = t >> 6;
    const int tt   = t & 63;

    __shared__ float a_nb[2][256];

    float4 acc0 = make_float4(0.f, 0.f, 0.f, 0.f);
    float4 acc1 = make_float4(0.f, 0.f, 0.f, 0.f);

    int e = start + half;
    for (; e + 2 < end; e += 4) {
        const int s0 = __ldg(&src_idx[e]);
        const int s1 = __ldg(&src_idx[e + 2]);
        const float4 v0 = *reinterpret_cast<const float4*>(&h[(size_t)s0 * 256 + tt * 4]);
        const float4 v1 = *reinterpret_cast<const float4*>(&h[(size_t)s1 * 256 + tt * 4]);
        acc0.x += v0.x; acc0.y += v0.y; acc0.z += v0.z; acc0.w += v0.w;
        acc1.x += v1.x; acc1.y += v1.y; acc1.z += v1.z; acc1.w += v1.w;
    }
    for (; e < end; e += 2) {
        const int s = __ldg(&src_idx[e]);
        const float4 v = *reinterpret_cast<const float4*>(&h[(size_t)s * 256 + tt * 4]);
        acc0.x += v.x; acc0.y += v.y; acc0.z += v.z; acc0.w += v.w;
    }
    acc0.x += acc1.x; acc0.y += acc1.y; acc0.z += acc1.z; acc0.w += acc1.w;
    *reinterpret_cast<float4*>(&a_nb[half][tt * 4]) = acc0;

    // self copy overlapped on stream-1 threads
    if (half == 1) {
        const float4 v = *reinterpret_cast<const float4*>(&h[(size_t)d * 256 + tt * 4]);
        store_h4(&A2[(size_t)d * 512 + tt * 4], v);
    }
    __syncthreads();

    if (half == 0) {
        const int deg = end - start;
        const float inv = (deg > 0) ? 1.0f / (float)deg : 0.0f;
        float4 u = *reinterpret_cast<float4*>(&a_nb[0][tt * 4]);
        const float4 w = *reinterpret_cast<float4*>(&a_nb[1][tt * 4]);
        u.x = (u.x + w.x) * inv; u.y = (u.y + w.y) * inv;
        u.z = (u.z + w.z) * inv; u.w = (u.w + w.w) * inv;
        store_h4(&A2[(size_t)d * 512 + 256 + tt * 4], u);
    }
}

// ---------------------------------------------------------------------------
// Merged weight transpose+convert.
// ---------------------------------------------------------------------------
__global__ __launch_bounds__(256) void wcvt_all_kernel(const float* __restrict__ Wself1,
                                                       const float* __restrict__ Wneigh1,
                                                       const float* __restrict__ Ws2,
                                                       const float* __restrict__ Wn2,
                                                       __half* __restrict__ WT,
                                                       __half* __restrict__ WT2)
{
    const int idx = blockIdx.x * 256 + threadIdx.x;
    if (idx < 256 * 512) {
        const int n = idx >> 9;
        const int k = idx & 511;
        const float v = (k < 256) ? __ldg(&Wself1[(size_t)k * 256 + n])
                                  : __ldg(&Wneigh1[(size_t)(k - 256) * 256 + n]);
        WT[(size_t)n * 512 + k] = __float2half_rn(v);
    } else {
        const int j = idx - 256 * 512;
        const int n = j >> 9;
        const int k = j & 511;
        float v = 0.f;
        if (n < C_DIM)
            v = (k < 256) ? __ldg(&Ws2[(size_t)k * C_DIM + n])
                          : __ldg(&Wn2[(size_t)(k - 256) * C_DIM + n]);
        WT2[(size_t)n * 512 + k] = __float2half_rn(v);
    }
}

// ---------------------------------------------------------------------------
// cp.async / ldmatrix helpers
// ---------------------------------------------------------------------------
__device__ __forceinline__ void cp_async16(uint32_t saddr, const void* g) {
    asm volatile("cp.async.ca.shared.global [%0], [%1], 16;\n" :: "r"(saddr), "l"(g));
}
__device__ __forceinline__ void cp_commit() {
    asm volatile("cp.async.commit_group;\n" ::: "memory");
}
__device__ __forceinline__ void ldsm_x4(uint32_t& r0, uint32_t& r1, uint32_t& r2, uint32_t& r3,
                                        uint32_t addr) {
    asm volatile("ldmatrix.sync.aligned.m8n8.x4.shared.b16 {%0,%1,%2,%3}, [%4];\n"
                 : "=r"(r0), "=r"(r1), "=r"(r2), "=r"(r3) : "r"(addr));
}
__device__ __forceinline__ void mma_f16(float c[4], const uint32_t a[4], const uint32_t b[2]) {
    asm volatile(
        "mma.sync.aligned.m16n8k16.row.col.f32.f16.f16.f32 "
        "{%0,%1,%2,%3}, {%4,%5,%6,%7}, {%8,%9}, {%0,%1,%2,%3};\n"
        : "+f"(c[0]), "+f"(c[1]), "+f"(c[2]), "+f"(c[3])
        : "r"(a[0]), "r"(a[1]), "r"(a[2]), "r"(a[3]), "r"(b[0]), "r"(b[1]));
}

// ---------------------------------------------------------------------------
// Shared fp16 MMA mainloop (CTA 128x64, BK=32, 3-stage cp.async ring).
// ---------------------------------------------------------------------------
#define G1_BM 128
#define G1_BN 64
#define G1_BK 32
#define SRW 20
#define OFF_A 0
#define OFF_B (G1_BM * SRW)
#define STAGE_WORDS ((G1_BM + G1_BN) * SRW)
#define N_KTILES 16

struct MmaCtx {
    float acc[2][4][4];
    int wm, wn, g, tg;
};

__device__ __forceinline__ void run_mma_tile(
    const __half* __restrict__ Abase,
    const __half* __restrict__ Bbase,
    uint32_t* smem, MmaCtx& ctx)
{
    const int tid  = threadIdx.x;
    const int warp = tid >> 5;
    const int lane = tid & 31;
    ctx.wm = warp >> 1;
    ctx.wn = warp & 1;
    ctx.g  = lane >> 2;
    ctx.tg = lane & 3;

    uint32_t sbase;
    asm("{ .reg .u64 t; cvta.to.shared.u64 t, %1; cvt.u32.u64 %0, t; }"
        : "=r"(sbase) : "l"(smem));

    const int a_row0 = tid >> 2;
    const int a_ch   = tid & 3;

    const __half* gA0 = Abase + (size_t)a_row0 * 512 + a_ch * 8;
    const __half* gA1 = Abase + (size_t)(a_row0 + 64) * 512 + a_ch * 8;
    const __half* gB  = Bbase + (size_t)a_row0 * 512 + a_ch * 8;

    const uint32_t sA0 = sbase + (OFF_A + a_row0 * SRW + a_ch * 4) * 4;
    const uint32_t sA1 = sbase + (OFF_A + (a_row0 + 64) * SRW + a_ch * 4) * 4;
    const uint32_t sB  = sbase + (OFF_B + a_row0 * SRW + a_ch * 4) * 4;

    uint32_t aAddr[2];
#pragma unroll
    for (int i = 0; i < 2; ++i) {
        const int row = ctx.wm * 32 + i * 16 + (lane & 15);
        const int word = (lane >> 4) * 4;
        aAddr[i] = sbase + (OFF_A + row * SRW + word) * 4;
    }
    uint32_t bAddr[2];
#pragma unroll
    for (int p = 0; p < 2; ++p) {
        const int row = ctx.wn * 32 + p * 16 + (lane & 7) + ((lane >> 4) << 3);
        const int word = ((lane >> 3) & 1) * 4;
        bAddr[p] = sbase + (OFF_B + row * SRW + word) * 4;
    }
    const uint32_t stage_bytes = STAGE_WORDS * 4;

#pragma unroll
    for (int i = 0; i < 2; ++i)
#pragma unroll
        for (int j = 0; j < 4; ++j)
#pragma unroll
            for (int r = 0; r < 4; ++r) ctx.acc[i][j][r] = 0.f;

#pragma unroll
    for (int pt = 0; pt < 2; ++pt) {
        const uint32_t so = pt * stage_bytes;
        const int kn = pt * G1_BK;
        cp_async16(sA0 + so, gA0 + kn);
        cp_async16(sA1 + so, gA1 + kn);
        cp_async16(sB + so,  gB + kn);
        cp_commit();
    }

    int stage = 0;
    for (int t = 0; t < N_KTILES; ++t) {
        if (t + 1 < N_KTILES)
            asm volatile("cp.async.wait_group 1;" ::: "memory");
        else
            asm volatile("cp.async.wait_group 0;" ::: "memory");
        __syncthreads();

        if (t + 2 < N_KTILES) {
            const int kn = (t + 2) * G1_BK;
            const uint32_t so = ((stage + 2) % 3) * stage_bytes;
            cp_async16(sA0 + so, gA0 + kn);
            cp_async16(sA1 + so, gA1 + kn);
            cp_async16(sB + so,  gB + kn);
            cp_commit();
        }

        const uint32_t so = stage * stage_bytes;
#pragma unroll
        for (int s = 0; s < 2; ++s) {
            const uint32_t ko = so + s * 32;
            uint32_t Af[2][4], Bf[2][4];
#pragma unroll
            for (int i = 0; i < 2; ++i)
                ldsm_x4(Af[i][0], Af[i][1], Af[i][2], Af[i][3], aAddr[i] + ko);
#pragma unroll
            for (int p = 0; p < 2; ++p)
                ldsm_x4(Bf[p][0], Bf[p][1], Bf[p][2], Bf[p][3], bAddr[p] + ko);
#pragma unroll
            for (int i = 0; i < 2; ++i)
#pragma unroll
                for (int j = 0; j < 4; ++j) {
                    const uint32_t bf[2] = { Bf[j >> 1][(j & 1) * 2], Bf[j >> 1][(j & 1) * 2 + 1] };
                    mma_f16(ctx.acc[i][j], Af[i], bf);
                }
        }
        stage = (stage + 1) % 3;
    }
}

// ---------------------------------------------------------------------------
// Layer-1 GEMM: h = relu(A @ WT^T + b1)
// ---------------------------------------------------------------------------
__global__ __launch_bounds__(256) void gemm1_kernel(
    const __half* __restrict__ A,
    const __half* __restrict__ WT,
    const float* __restrict__ bias,
    float* __restrict__ out)
{
    __shared__ __align__(16) uint32_t smem[3 * STAGE_WORDS];
    const int bx = blockIdx.x;
    const int by = blockIdx.y;

    MmaCtx ctx;
    run_mma_tile(A + (size_t)(by * G1_BM) * 512, WT + (size_t)(bx * G1_BN) * 512, smem, ctx);

#pragma unroll
    for (int i = 0; i < 2; ++i) {
#pragma unroll
        for (int j = 0; j < 4; ++j) {
            const int col = bx * G1_BN + ctx.wn * 32 + j * 8 + ctx.tg * 2;
            const float b0 = __ldg(&bias[col]);
            const float b1 = __ldg(&bias[col + 1]);
            const int r0 = by * G1_BM + ctx.wm * 32 + i * 16 + ctx.g;
            float2 v0;
            v0.x = fmaxf(ctx.acc[i][j][0] + b0, 0.f);
            v0.y = fmaxf(ctx.acc[i][j][1] + b1, 0.f);
            *reinterpret_cast<float2*>(&out[(size_t)r0 * 256 + col]) = v0;
            float2 v1;
            v1.x = fmaxf(ctx.acc[i][j][2] + b0, 0.f);
            v1.y = fmaxf(ctx.acc[i][j][3] + b1, 0.f);
            *reinterpret_cast<float2*>(&out[(size_t)(r0 + 8) * 256 + col]) = v1;
        }
    }
}

// ---------------------------------------------------------------------------
// Layer-2 GEMM: out = A2 @ WT2^T + b2 (no relu), cols >= 47 dropped.
// ---------------------------------------------------------------------------
__global__ __launch_bounds__(256) void gemm2_tc_kernel(
    const __half* __restrict__ A2,
    const __half* __restrict__ WT2,
    const float* __restrict__ bias,
    float* __restrict__ out)
{
    __shared__ __align__(16) uint32_t smem[3 * STAGE_WORDS];
    const int by = blockIdx.x;

    MmaCtx ctx;
    run_mma_tile(A2 + (size_t)(by * G1_BM) * 512, WT2, smem, ctx);

#pragma unroll
    for (int i = 0; i < 2; ++i) {
#pragma unroll
        for (int j = 0; j < 4; ++j) {
            const int col = ctx.wn * 32 + j * 8 + ctx.tg * 2;
            const int r0 = by * G1_BM + ctx.wm * 32 + i * 16 + ctx.g;
            if (col < C_DIM) {
                const float b0 = __ldg(&bias[col]);
                out[(size_t)r0 * C_DIM + col]       = ctx.acc[i][j][0] + b0;
                out[(size_t)(r0 + 8) * C_DIM + col] = ctx.acc[i][j][2] + b0;
            }
            if (col + 1 < C_DIM) {
                const float b1 = __ldg(&bias[col + 1]);
                out[(size_t)r0 * C_DIM + col + 1]       = ctx.acc[i][j][1] + b1;
                out[(size_t)(r0 + 8) * C_DIM + col + 1] = ctx.acc[i][j][3] + b1;
            }
        }
    }
}

// ---------------------------------------------------------------------------
// Launch
// ---------------------------------------------------------------------------
extern "C" void kernel_launch(void* const* d_in, const int* in_sizes, int n_in,
                              void* d_out, int out_size)
{
    const float* x       = (const float*)d_in[0];
    const int*   src1    = (const int*)  d_in[1];
    const int*   dst1    = (const int*)  d_in[2];
    const int*   src2    = (const int*)  d_in[3];
    const int*   dst2    = (const int*)  d_in[4];
    const float* Wself1  = (const float*)d_in[5];
    const float* Wneigh1 = (const float*)d_in[6];
    const float* b1      = (const float*)d_in[7];
    const float* Wself2  = (const float*)d_in[8];
    const float* Wneigh2 = (const float*)d_in[9];
    const float* b2      = (const float*)d_in[10];
    float* out = (float*)d_out;

    __half *A, *WT, *A2, *WT2;
    float* hbuf;
    cudaGetSymbolAddress((void**)&A,   g_A);
    cudaGetSymbolAddress((void**)&WT,  g_WT);
    cudaGetSymbolAddress((void**)&A2,  g_A2);
    cudaGetSymbolAddress((void**)&WT2, g_WT2);
    cudaGetSymbolAddress((void**)&hbuf, g_h);

    // Prep: merged weight transpose+convert (both layers)
    wcvt_all_kernel<<<(320 * 512) / 256, 256>>>(Wself1, Wneigh1, Wself2, Wneigh2, WT, WT2);

    // Layer 1: aggregation + fused x convert
    agg1_kernel<<<N_DST1, 128>>>(x, src1, dst1, A);

    // Layer 1 GEMM + bias + relu
    dim3 g1(H_DIM / G1_BN, N_DST1 / G1_BM);   // (4, 88)
    gemm1_kernel<<<g1, 256>>>(A, WT, b1, hbuf);

    // Layer 2: aggregate + GEMM
    agg2_kernel<<<N_DST2, 128>>>(hbuf, src2, dst2, A2);
    gemm2_tc_kernel<<<N_DST2 / G1_BM, 256>>>(A2, WT2, b2, out);
}

// round 15
// speedup vs baseline: 1.3100x; 1.0011x over previous
#include <cuda_runtime.h>
#include <cuda_fp16.h>
#include <cstdint>

// Problem constants
#define N_SRC1  292864
#define N_DST1  11264
#define N_E1    281600
#define N_DST2  1024
#define N_E2    10240
#define IN_DIM  256
#define H_DIM   256
#define C_DIM   47

// Scratch (device globals — no allocation allowed)
__device__ __half g_A[N_DST1 * 512];      // [x_dst | hneigh1] fp16
__device__ __half g_WT[256 * 512];        // [Wself1;Wneigh1]^T fp16
__device__ float  g_h[N_DST1 * H_DIM];    // relu(layer-1 out) fp32
__device__ __half g_A2[N_DST2 * 512];     // [h_dst | hneigh2] fp16
__device__ __half g_WT2[64 * 512];        // [Wself2;Wneigh2]^T fp16, cols 47-63 zero

// ---------------------------------------------------------------------------
// fp16 helpers
// ---------------------------------------------------------------------------
__device__ __forceinline__ uint32_t pack_h2(float f0, float f1) {
    const __half h0 = __float2half_rn(f0);
    const __half h1 = __float2half_rn(f1);
    return (uint32_t)__half_as_ushort(h0) | ((uint32_t)__half_as_ushort(h1) << 16);
}
__device__ __forceinline__ void store_h4(__half* p, float4 v) {
    uint2 u;
    u.x = pack_h2(v.x, v.y);
    u.y = pack_h2(v.z, v.w);
    *reinterpret_cast<uint2*>(p) = u;
}

// ---------------------------------------------------------------------------
// Layer-1 mean aggregation + self-row convert (fused xcvt):
// 128 thr/dst, 2 edge streams, 2x unroll, regs capped for full occupancy.
// ---------------------------------------------------------------------------
__global__ __launch_bounds__(128, 16) void agg1_kernel(const float* __restrict__ feat,
                                                       const int* __restrict__ src_idx,
                                                       const int* __restrict__ dst_idx,
                                                       __half* __restrict__ A)
{
    const int d = blockIdx.x;

    int lo = 0, hi = N_E1;
    while (lo < hi) { int mid = (lo + hi) >> 1; if (__ldg(&dst_idx[mid]) < d) lo = mid + 1; else hi = mid; }
    const int start = lo;
    hi = N_E1;
    while (lo < hi) { int mid = (lo + hi) >> 1; if (__ldg(&dst_idx[mid]) <= d) lo = mid + 1; else hi = mid; }
    const int end = lo;

    const int t    = threadIdx.x;
    const int half = t >> 6;            // 0/1 edge stream
    const int tt   = t & 63;            // float4 slice of the 256-dim row

    __shared__ float a_nb[2][256];

    float4 acc0 = make_float4(0.f, 0.f, 0.f, 0.f);
    float4 acc1 = make_float4(0.f, 0.f, 0.f, 0.f);

    int e = start + half;
    for (; e + 2 < end; e += 4) {
        const int s0 = __ldg(&src_idx[e]);
        const int s1 = __ldg(&src_idx[e + 2]);
        const float4 v0 = *reinterpret_cast<const float4*>(&feat[(size_t)s0 * 256 + tt * 4]);
        const float4 v1 = *reinterpret_cast<const float4*>(&feat[(size_t)s1 * 256 + tt * 4]);
        acc0.x += v0.x; acc0.y += v0.y; acc0.z += v0.z; acc0.w += v0.w;
        acc1.x += v1.x; acc1.y += v1.y; acc1.z += v1.z; acc1.w += v1.w;
    }
    for (; e < end; e += 2) {
        const int s = __ldg(&src_idx[e]);
        const float4 v = *reinterpret_cast<const float4*>(&feat[(size_t)s * 256 + tt * 4]);
        acc0.x += v.x; acc0.y += v.y; acc0.z += v.z; acc0.w += v.w;
    }
    acc0.x += acc1.x; acc0.y += acc1.y; acc0.z += acc1.z; acc0.w += acc1.w;
    *reinterpret_cast<float4*>(&a_nb[half][tt * 4]) = acc0;

    // fused xcvt: stream-1 threads convert the self row while stream-0 reduces
    if (half == 1) {
        const float4 v = *reinterpret_cast<const float4*>(&feat[(size_t)d * 256 + tt * 4]);
        store_h4(&A[(size_t)d * 512 + tt * 4], v);
    }
    __syncthreads();

    if (half == 0) {
        const int deg = end - start;
        const float inv = (deg > 0) ? 1.0f / (float)deg : 0.0f;
        float4 u = *reinterpret_cast<float4*>(&a_nb[0][tt * 4]);
        const float4 w = *reinterpret_cast<float4*>(&a_nb[1][tt * 4]);
        u.x = (u.x + w.x) * inv; u.y = (u.y + w.y) * inv;
        u.z = (u.z + w.z) * inv; u.w = (u.w + w.w) * inv;
        store_h4(&A[(size_t)d * 512 + 256 + tt * 4], u);
    }
}

// ---------------------------------------------------------------------------
// Layer-2 aggregation + self copy: 1024 blocks x 256 thr, 4 edge streams,
// 2x unroll, self-copy on stream 1, regs capped for occupancy.
// ---------------------------------------------------------------------------
__global__ __launch_bounds__(256, 8) void agg2_kernel(const float* __restrict__ h,
                                                      const int* __restrict__ src_idx,
                                                      const int* __restrict__ dst_idx,
                                                      __half* __restrict__ A2)
{
    const int d = blockIdx.x;

    int lo = 0, hi = N_E2;
    while (lo < hi) { int mid = (lo + hi) >> 1; if (__ldg(&dst_idx[mid]) < d) lo = mid + 1; else hi = mid; }
    const int start = lo;
    hi = N_E2;
    while (lo < hi) { int mid = (lo + hi) >> 1; if (__ldg(&dst_idx[mid]) <= d) lo = mid + 1; else hi = mid; }
    const int end = lo;

    const int t  = threadIdx.x;
    const int qs = t >> 6;              // 0..3 edge stream
    const int tt = t & 63;              // float4 slice

    __shared__ float a_nb[4][256];

    float4 acc0 = make_float4(0.f, 0.f, 0.f, 0.f);
    float4 acc1 = make_float4(0.f, 0.f, 0.f, 0.f);

    int e = start + qs;
    for (; e + 4 < end; e += 8) {
        const int s0 = __ldg(&src_idx[e]);
        const int s1 = __ldg(&src_idx[e + 4]);
        const float4 v0 = *reinterpret_cast<const float4*>(&h[(size_t)s0 * 256 + tt * 4]);
        const float4 v1 = *reinterpret_cast<const float4*>(&h[(size_t)s1 * 256 + tt * 4]);
        acc0.x += v0.x; acc0.y += v0.y; acc0.z += v0.z; acc0.w += v0.w;
        acc1.x += v1.x; acc1.y += v1.y; acc1.z += v1.z; acc1.w += v1.w;
    }
    for (; e < end; e += 4) {
        const int s = __ldg(&src_idx[e]);
        const float4 v = *reinterpret_cast<const float4*>(&h[(size_t)s * 256 + tt * 4]);
        acc0.x += v.x; acc0.y += v.y; acc0.z += v.z; acc0.w += v.w;
    }
    acc0.x += acc1.x; acc0.y += acc1.y; acc0.z += acc1.z; acc0.w += acc1.w;
    *reinterpret_cast<float4*>(&a_nb[qs][tt * 4]) = acc0;

    // self copy overlapped on stream-1 threads
    if (qs == 1) {
        const float4 v = *reinterpret_cast<const float4*>(&h[(size_t)d * 256 + tt * 4]);
        store_h4(&A2[(size_t)d * 512 + tt * 4], v);
    }
    __syncthreads();

    if (qs == 0) {
        const int deg = end - start;
        const float inv = (deg > 0) ? 1.0f / (float)deg : 0.0f;
        float4 u = *reinterpret_cast<float4*>(&a_nb[0][tt * 4]);
        const float4 w1 = *reinterpret_cast<float4*>(&a_nb[1][tt * 4]);
        const float4 w2 = *reinterpret_cast<float4*>(&a_nb[2][tt * 4]);
        const float4 w3 = *reinterpret_cast<float4*>(&a_nb[3][tt * 4]);
        u.x = (u.x + w1.x + w2.x + w3.x) * inv;
        u.y = (u.y + w1.y + w2.y + w3.y) * inv;
        u.z = (u.z + w1.z + w2.z + w3.z) * inv;
        u.w = (u.w + w1.w + w2.w + w3.w) * inv;
        store_h4(&A2[(size_t)d * 512 + 256 + tt * 4], u);
    }
}

// ---------------------------------------------------------------------------
// Merged weight transpose+convert.
// ---------------------------------------------------------------------------
__global__ __launch_bounds__(256) void wcvt_all_kernel(const float* __restrict__ Wself1,
                                                       const float* __restrict__ Wneigh1,
                                                       const float* __restrict__ Ws2,
                                                       const float* __restrict__ Wn2,
                                                       __half* __restrict__ WT,
                                                       __half* __restrict__ WT2)
{
    const int idx = blockIdx.x * 256 + threadIdx.x;
    if (idx < 256 * 512) {
        const int n = idx >> 9;
        const int k = idx & 511;
        const float v = (k < 256) ? __ldg(&Wself1[(size_t)k * 256 + n])
                                  : __ldg(&Wneigh1[(size_t)(k - 256) * 256 + n]);
        WT[(size_t)n * 512 + k] = __float2half_rn(v);
    } else {
        const int j = idx - 256 * 512;
        const int n = j >> 9;
        const int k = j & 511;
        float v = 0.f;
        if (n < C_DIM)
            v = (k < 256) ? __ldg(&Ws2[(size_t)k * C_DIM + n])
                          : __ldg(&Wn2[(size_t)(k - 256) * C_DIM + n]);
        WT2[(size_t)n * 512 + k] = __float2half_rn(v);
    }
}

// ---------------------------------------------------------------------------
// cp.async / ldmatrix helpers
// ---------------------------------------------------------------------------
__device__ __forceinline__ void cp_async16(uint32_t saddr, const void* g) {
    asm volatile("cp.async.ca.shared.global [%0], [%1], 16;\n" :: "r"(saddr), "l"(g));
}
__device__ __forceinline__ void cp_commit() {
    asm volatile("cp.async.commit_group;\n" ::: "memory");
}
__device__ __forceinline__ void ldsm_x4(uint32_t& r0, uint32_t& r1, uint32_t& r2, uint32_t& r3,
                                        uint32_t addr) {
    asm volatile("ldmatrix.sync.aligned.m8n8.x4.shared.b16 {%0,%1,%2,%3}, [%4];\n"
                 : "=r"(r0), "=r"(r1), "=r"(r2), "=r"(r3) : "r"(addr));
}
__device__ __forceinline__ void mma_f16(float c[4], const uint32_t a[4], const uint32_t b[2]) {
    asm volatile(
        "mma.sync.aligned.m16n8k16.row.col.f32.f16.f16.f32 "
        "{%0,%1,%2,%3}, {%4,%5,%6,%7}, {%8,%9}, {%0,%1,%2,%3};\n"
        : "+f"(c[0]), "+f"(c[1]), "+f"(c[2]), "+f"(c[3])
        : "r"(a[0]), "r"(a[1]), "r"(a[2]), "r"(a[3]), "r"(b[0]), "r"(b[1]));
}

// ---------------------------------------------------------------------------
// Shared fp16 MMA mainloop (CTA 128x64, BK=32, 3-stage cp.async ring).
// ---------------------------------------------------------------------------
#define G1_BM 128
#define G1_BN 64
#define G1_BK 32
#define SRW 20
#define OFF_A 0
#define OFF_B (G1_BM * SRW)
#define STAGE_WORDS ((G1_BM + G1_BN) * SRW)
#define N_KTILES 16

struct MmaCtx {
    float acc[2][4][4];
    int wm, wn, g, tg;
};

__device__ __forceinline__ void run_mma_tile(
    const __half* __restrict__ Abase,
    const __half* __restrict__ Bbase,
    uint32_t* smem, MmaCtx& ctx)
{
    const int tid  = threadIdx.x;
    const int warp = tid >> 5;
    const int lane = tid & 31;
    ctx.wm = warp >> 1;
    ctx.wn = warp & 1;
    ctx.g  = lane >> 2;
    ctx.tg = lane & 3;

    uint32_t sbase;
    asm("{ .reg .u64 t; cvta.to.shared.u64 t, %1; cvt.u32.u64 %0, t; }"
        : "=r"(sbase) : "l"(smem));

    const int a_row0 = tid >> 2;
    const int a_ch   = tid & 3;

    const __half* gA0 = Abase + (size_t)a_row0 * 512 + a_ch * 8;
    const __half* gA1 = Abase + (size_t)(a_row0 + 64) * 512 + a_ch * 8;
    const __half* gB  = Bbase + (size_t)a_row0 * 512 + a_ch * 8;

    const uint32_t sA0 = sbase + (OFF_A + a_row0 * SRW + a_ch * 4) * 4;
    const uint32_t sA1 = sbase + (OFF_A + (a_row0 + 64) * SRW + a_ch * 4) * 4;
    const uint32_t sB  = sbase + (OFF_B + a_row0 * SRW + a_ch * 4) * 4;

    uint32_t aAddr[2];
#pragma unroll
    for (int i = 0; i < 2; ++i) {
        const int row = ctx.wm * 32 + i * 16 + (lane & 15);
        const int word = (lane >> 4) * 4;
        aAddr[i] = sbase + (OFF_A + row * SRW + word) * 4;
    }
    uint32_t bAddr[2];
#pragma unroll
    for (int p = 0; p < 2; ++p) {
        const int row = ctx.wn * 32 + p * 16 + (lane & 7) + ((lane >> 4) << 3);
        const int word = ((lane >> 3) & 1) * 4;
        bAddr[p] = sbase + (OFF_B + row * SRW + word) * 4;
    }
    const uint32_t stage_bytes = STAGE_WORDS * 4;

#pragma unroll
    for (int i = 0; i < 2; ++i)
#pragma unroll
        for (int j = 0; j < 4; ++j)
#pragma unroll
            for (int r = 0; r < 4; ++r) ctx.acc[i][j][r] = 0.f;

#pragma unroll
    for (int pt = 0; pt < 2; ++pt) {
        const uint32_t so = pt * stage_bytes;
        const int kn = pt * G1_BK;
        cp_async16(sA0 + so, gA0 + kn);
        cp_async16(sA1 + so, gA1 + kn);
        cp_async16(sB + so,  gB + kn);
        cp_commit();
    }

    int stage = 0;
    for (int t = 0; t < N_KTILES; ++t) {
        if (t + 1 < N_KTILES)
            asm volatile("cp.async.wait_group 1;" ::: "memory");
        else
            asm volatile("cp.async.wait_group 0;" ::: "memory");
        __syncthreads();

        if (t + 2 < N_KTILES) {
            const int kn = (t + 2) * G1_BK;
            const uint32_t so = ((stage + 2) % 3) * stage_bytes;
            cp_async16(sA0 + so, gA0 + kn);
            cp_async16(sA1 + so, gA1 + kn);
            cp_async16(sB + so,  gB + kn);
            cp_commit();
        }

        const uint32_t so = stage * stage_bytes;
#pragma unroll
        for (int s = 0; s < 2; ++s) {
            const uint32_t ko = so + s * 32;
            uint32_t Af[2][4], Bf[2][4];
#pragma unroll
            for (int i = 0; i < 2; ++i)
                ldsm_x4(Af[i][0], Af[i][1], Af[i][2], Af[i][3], aAddr[i] + ko);
#pragma unroll
            for (int p = 0; p < 2; ++p)
                ldsm_x4(Bf[p][0], Bf[p][1], Bf[p][2], Bf[p][3], bAddr[p] + ko);
#pragma unroll
            for (int i = 0; i < 2; ++i)
#pragma unroll
                for (int j = 0; j < 4; ++j) {
                    const uint32_t bf[2] = { Bf[j >> 1][(j & 1) * 2], Bf[j >> 1][(j & 1) * 2 + 1] };
                    mma_f16(ctx.acc[i][j], Af[i], bf);
                }
        }
        stage = (stage + 1) % 3;
    }
}

// ---------------------------------------------------------------------------
// Layer-1 GEMM: h = relu(A @ WT^T + b1)
// ---------------------------------------------------------------------------
__global__ __launch_bounds__(256) void gemm1_kernel(
    const __half* __restrict__ A,
    const __half* __restrict__ WT,
    const float* __restrict__ bias,
    float* __restrict__ out)
{
    __shared__ __align__(16) uint32_t smem[3 * STAGE_WORDS];
    const int bx = blockIdx.x;
    const int by = blockIdx.y;

    MmaCtx ctx;
    run_mma_tile(A + (size_t)(by * G1_BM) * 512, WT + (size_t)(bx * G1_BN) * 512, smem, ctx);

#pragma unroll
    for (int i = 0; i < 2; ++i) {
#pragma unroll
        for (int j = 0; j < 4; ++j) {
            const int col = bx * G1_BN + ctx.wn * 32 + j * 8 + ctx.tg * 2;
            const float b0 = __ldg(&bias[col]);
            const float b1 = __ldg(&bias[col + 1]);
            const int r0 = by * G1_BM + ctx.wm * 32 + i * 16 + ctx.g;
            float2 v0;
            v0.x = fmaxf(ctx.acc[i][j][0] + b0, 0.f);
            v0.y = fmaxf(ctx.acc[i][j][1] + b1, 0.f);
            *reinterpret_cast<float2*>(&out[(size_t)r0 * 256 + col]) = v0;
            float2 v1;
            v1.x = fmaxf(ctx.acc[i][j][2] + b0, 0.f);
            v1.y = fmaxf(ctx.acc[i][j][3] + b1, 0.f);
            *reinterpret_cast<float2*>(&out[(size_t)(r0 + 8) * 256 + col]) = v1;
        }
    }
}

// ---------------------------------------------------------------------------
// Layer-2 GEMM: out = A2 @ WT2^T + b2 (no relu), cols >= 47 dropped.
// ---------------------------------------------------------------------------
__global__ __launch_bounds__(256) void gemm2_tc_kernel(
    const __half* __restrict__ A2,
    const __half* __restrict__ WT2,
    const float* __restrict__ bias,
    float* __restrict__ out)
{
    __shared__ __align__(16) uint32_t smem[3 * STAGE_WORDS];
    const int by = blockIdx.x;

    MmaCtx ctx;
    run_mma_tile(A2 + (size_t)(by * G1_BM) * 512, WT2, smem, ctx);

#pragma unroll
    for (int i = 0; i < 2; ++i) {
#pragma unroll
        for (int j = 0; j < 4; ++j) {
            const int col = ctx.wn * 32 + j * 8 + ctx.tg * 2;
            const int r0 = by * G1_BM + ctx.wm * 32 + i * 16 + ctx.g;
            if (col < C_DIM) {
                const float b0 = __ldg(&bias[col]);
                out[(size_t)r0 * C_DIM + col]       = ctx.acc[i][j][0] + b0;
                out[(size_t)(r0 + 8) * C_DIM + col] = ctx.acc[i][j][2] + b0;
            }
            if (col + 1 < C_DIM) {
                const float b1 = __ldg(&bias[col + 1]);
                out[(size_t)r0 * C_DIM + col + 1]       = ctx.acc[i][j][1] + b1;
                out[(size_t)(r0 + 8) * C_DIM + col + 1] = ctx.acc[i][j][3] + b1;
            }
        }
    }
}

// ---------------------------------------------------------------------------
// Launch
// ---------------------------------------------------------------------------
extern "C" void kernel_launch(void* const* d_in, const int* in_sizes, int n_in,
                              void* d_out, int out_size)
{
    const float* x       = (const float*)d_in[0];
    const int*   src1    = (const int*)  d_in[1];
    const int*   dst1    = (const int*)  d_in[2];
    const int*   src2    = (const int*)  d_in[3];
    const int*   dst2    = (const int*)  d_in[4];
    const float* Wself1  = (const float*)d_in[5];
    const float* Wneigh1 = (const float*)d_in[6];
    const float* b1      = (const float*)d_in[7];
    const float* Wself2  = (const float*)d_in[8];
    const float* Wneigh2 = (const float*)d_in[9];
    const float* b2      = (const float*)d_in[10];
    float* out = (float*)d_out;

    __half *A, *WT, *A2, *WT2;
    float* hbuf;
    cudaGetSymbolAddress((void**)&A,   g_A);
    cudaGetSymbolAddress((void**)&WT,  g_WT);
    cudaGetSymbolAddress((void**)&A2,  g_A2);
    cudaGetSymbolAddress((void**)&WT2, g_WT2);
    cudaGetSymbolAddress((void**)&hbuf, g_h);

    // Prep: merged weight transpose+convert (both layers)
    wcvt_all_kernel<<<(320 * 512) / 256, 256>>>(Wself1, Wneigh1, Wself2, Wneigh2, WT, WT2);

    // Layer 1: aggregation + fused x convert
    agg1_kernel<<<N_DST1, 128>>>(x, src1, dst1, A);

    // Layer 1 GEMM + bias + relu
    dim3 g1(H_DIM / G1_BN, N_DST1 / G1_BM);   // (4, 88)
    gemm1_kernel<<<g1, 256>>>(A, WT, b1, hbuf);

    // Layer 2: aggregate + GEMM
    agg2_kernel<<<N_DST2, 256>>>(hbuf, src2, dst2, A2);
    gemm2_tc_kernel<<<N_DST2 / G1_BM, 256>>>(A2, WT2, b2, out);
}